// round 8
// baseline (speedup 1.0000x reference)
#include <cuda_runtime.h>
#include <math.h>
#include <stdint.h>

// ---------------------------------------------------------------------------
// B=8, T=10, H=W=64, Cin=1, F=64, 4F=256, k=3x3 SAME.
// Output: [2][2][8][64][64][64] fp32.
// tf32 mma.sync (m16n8k8) implicit-GEMM conv.
// Per block: M=64 positions (one image row) x N=256 gates, K=576 as 18 stages
// (9 taps x 2 chunks of 32 ch). A (3 h-rows) persistent in smem, XOR-swizzled.
// B pre-laid in fragment order in gmem by prep_w -> linear cp.async, float2 LDS.
// ---------------------------------------------------------------------------

#define HW    64
#define FDIM  64
#define C4    256
#define NPIX  4096
#define SEG   2097152            // 8*4096*64

__device__ float g_xg0[10 * 8 * NPIX * C4];
__device__ float g_xg1[10 * 8 * NPIX * C4];
__device__ float g_out0[10 * 8 * NPIX * FDIM];
__device__ float g_h[2][SEG];
__device__ float g_c[SEG];
__device__ float g_wt[3 * 576 * 256];   // fragment-ordered tf32 Wh0 / Wx1 / Wh1

__device__ __forceinline__ float hsig(float x) {
    return fminf(fmaxf(0.2f * x + 0.5f, 0.0f), 1.0f);
}
__device__ __forceinline__ float tf32r(float v) {
    unsigned u;
    asm("cvt.rna.tf32.f32 %0, %1;" : "=r"(u) : "f"(v));
    return __uint_as_float(u);
}
__device__ __forceinline__ unsigned smem_u32(const void* p) {
    unsigned r;
    asm("{ .reg .u64 t; cvta.to.shared.u64 t, %1; cvt.u32.u64 %0, t; }"
        : "=r"(r) : "l"(p));
    return r;
}

#define MMA_TF32(c, a, b0v, b1v)                                               \
    asm volatile("mma.sync.aligned.m16n8k8.row.col.f32.tf32.tf32.f32 "         \
        "{%0,%1,%2,%3}, {%4,%5,%6,%7}, {%8,%9}, {%0,%1,%2,%3};"                \
        : "+f"(c[0]), "+f"(c[1]), "+f"(c[2]), "+f"(c[3])                       \
        : "r"(a[0]), "r"(a[1]), "r"(a[2]), "r"(a[3]), "r"(b0v), "r"(b1v))

// smem layout (floats): HROW [3][64][64] swizzled @0; B frag bufs @12288/@20480
#define HROWF 0
#define BF0   12288
#define BF1   20480
#define SMEMF 28672
#define SMEM_BYTES (SMEMF * 4)       // 114688 -> 2 blocks/SM

// ---------------------------------------------------------------------------
__global__ void zero_hc() {
    int i = blockIdx.x * blockDim.x + threadIdx.x;
    if (i < SEG) { g_h[0][i] = 0.0f; g_c[i] = 0.0f; }
}
__global__ void gather_out(float* __restrict__ out, int layer) {
    int i = blockIdx.x * blockDim.x + threadIdx.x;
    if (i < SEG) {
        out[(size_t)layer * 2 * SEG + i]       = g_h[0][i];
        out[(size_t)layer * 2 * SEG + SEG + i] = g_c[i];
    }
}

// Rewrite the three 64->256 weight tensors into MMA B-fragment order, tf32:
// float2[which][s(18)][kf(4)][ct(32)][lane(32)] =
//   { W[s*32+kf*8+tg][ct*8+g], W[s*32+kf*8+tg+4][ct*8+g] },  g=lane>>2, tg=lane&3
__global__ void prep_w(const float* __restrict__ w0, const float* __restrict__ w1,
                       const float* __restrict__ w2) {
    int idx = blockIdx.x * 256 + threadIdx.x;      // float2 index
    if (idx >= 3 * 73728) return;
    int which = idx / 73728;
    int rem   = idx - which * 73728;
    int s  = rem >> 12;
    int r2 = rem & 4095;
    int kf = r2 >> 10;
    int ct = (r2 >> 5) & 31;
    int ln = r2 & 31;
    int tg = ln & 3, gg = ln >> 2;
    const float* src = (which == 0) ? w0 : (which == 1) ? w1 : w2;
    int r0  = s * 32 + kf * 8 + tg;
    int col = ct * 8 + gg;
    float2 v;
    v.x = tf32r(src[(size_t)r0 * 256 + col]);
    v.y = tf32r(src[(size_t)(r0 + 4) * 256 + col]);
    ((float2*)g_wt)[idx] = v;
}

// Layer-0 input conv (Cin=1), exact fp32: xg0[img][pix][256] = b0 + conv(x, Wx0)
__global__ void conv_l0(const float* __restrict__ x, const float* __restrict__ w,
                        const float* __restrict__ b, float* __restrict__ xg) {
    __shared__ float ps[18 * 18];
    __shared__ float ws[9 * C4];
    int img = blockIdx.y;
    int by0 = (blockIdx.x >> 2) * 16, bx0 = (blockIdx.x & 3) * 16;
    int tid = threadIdx.x;
    for (int i = tid; i < 324; i += 256) {
        int ly = i / 18, lx = i - ly * 18;
        int gy = by0 + ly - 1, gx = bx0 + lx - 1;
        float v = 0.0f;
        if (gy >= 0 && gy < HW && gx >= 0 && gx < HW)
            v = x[(size_t)img * NPIX + gy * HW + gx];
        ps[i] = v;
    }
    for (int i = tid; i < 9 * C4; i += 256) ws[i] = w[i];
    __syncthreads();
    float wr[9];
#pragma unroll
    for (int tp = 0; tp < 9; ++tp) wr[tp] = ws[tp * C4 + tid];
    float bv = b[tid];
    for (int p = 0; p < 256; ++p) {
        int py = p >> 4, px = p & 15;
        float a = bv;
#pragma unroll
        for (int tp = 0; tp < 9; ++tp) {
            int dy = tp / 3, dx = tp - 3 * dy;
            a += ps[(py + dy) * 18 + (px + dx)] * wr[tp];
        }
        xg[((size_t)img * NPIX + (by0 + py) * HW + (bx0 + px)) * C4 + tid] = a;
    }
}

// ---------------------------------------------------------------------------
// tf32 mma.sync conv block. MODE 1: LSTM step; MODE 0: gates = conv + bias.
// 8 warps as 2(M) x 4(N); warp tile 32x64; 64 fp32 accumulators per thread.
// ---------------------------------------------------------------------------
template <int MODE>
__global__ void __launch_bounds__(256, 2)
mm_conv(const float* __restrict__ in, const float* __restrict__ wt,
        const float* __restrict__ xg_or_bias, float* __restrict__ gout,
        float* __restrict__ cbuf, float* __restrict__ hout,
        float* __restrict__ outseq, int tstep) {
    extern __shared__ float smf[];
    unsigned sbase = smem_u32(smf);
    int tid = threadIdx.x;
    int wid = tid >> 5, lane = tid & 31;
    int g = lane >> 2, tg = lane & 3;
    int mw = wid >> 2, nw = wid & 3;
    int m_base = mw * 32, n_base = nw * 64;
    int img = blockIdx.y;
    int y0 = blockIdx.x;                       // image row handled by block
    const float* inb = in + (size_t)img * (NPIX * FDIM);

    // ---- fill persistent A: 3 rows x 64 pos x 64 ch, tf32, XOR-swizzled ----
    // layout: smf[ ((dyi*64 + x)*64) + (c ^ ((x&7)<<2)) ]
    for (int i = tid; i < 3072; i += 256) {          // 3072 float4
        int dyi = i >> 10;
        int rem = i & 1023;
        int xx = rem >> 4;
        int c4 = (rem & 15) << 2;
        int y = y0 + dyi - 1;
        float4 v = make_float4(0.f, 0.f, 0.f, 0.f);
        if ((unsigned)y < 64u)
            v = *(const float4*)(inb + (size_t)(((y << 6) + xx) * 64 + c4));
        v.x = tf32r(v.x); v.y = tf32r(v.y); v.z = tf32r(v.z); v.w = tf32r(v.w);
        int cs = c4 ^ ((xx & 7) << 2);
        *(float4*)(smf + (((dyi << 6) + xx) << 6) + cs) = v;
    }

    float acc[2][8][4];
#pragma unroll
    for (int mi = 0; mi < 2; ++mi)
#pragma unroll
        for (int ni = 0; ni < 8; ++ni)
#pragma unroll
            for (int r = 0; r < 4; ++r) acc[mi][ni][r] = 0.0f;

    auto issueB = [&](int s, int buf) {
        const float4* wp = (const float4*)(wt + (size_t)s * 8192);
        unsigned dbase = sbase + (unsigned)(BF0 + buf * 8192) * 4;
#pragma unroll
        for (int i = 0; i < 8; ++i) {
            int idx = tid + i * 256;
            unsigned daddr = dbase + (unsigned)idx * 16;
            asm volatile("cp.async.ca.shared.global [%0], [%1], 16;"
                         :: "r"(daddr), "l"(wp + idx));
        }
    };

    issueB(0, 0);
    asm volatile("cp.async.commit_group;");
    issueB(1, 1);
    asm volatile("cp.async.commit_group;");

    for (int s = 0; s < 18; ++s) {
        int cur = s & 1;
        if (s < 17) asm volatile("cp.async.wait_group 1;");
        else        asm volatile("cp.async.wait_group 0;");
        __syncthreads();    // B(s) visible; hrow ready (s=0); prev issue safe

        int tap = s >> 1, ch0 = (s & 1) << 5;
        int qy = tap / 3;
        int dyi = qy;                       // dy+1
        int dx = tap - 3 * qy - 1;
        int sw = ((g + dx) & 7) << 2;
        const float* Bb = smf + BF0 + cur * 8192;
        int pl0 = m_base + g + dx;

#pragma unroll
        for (int kf = 0; kf < 4; ++kf) {
            int c0 = ch0 + (kf << 3) + tg;
            int ci0 = c0 ^ sw;
            int ci4 = (c0 + 4) ^ sw;
            unsigned a[2][4];
#pragma unroll
            for (int mi = 0; mi < 2; ++mi) {
                int pl = pl0 + mi * 16;
                const float* rb = smf + (((dyi << 6) + pl) << 6);
                bool okl = (unsigned)pl < 64u;
                bool okh = (unsigned)(pl + 8) < 64u;
                a[mi][0] = okl ? __float_as_uint(rb[ci0])       : 0u;
                a[mi][1] = okh ? __float_as_uint(rb[512 + ci0]) : 0u;
                a[mi][2] = okl ? __float_as_uint(rb[ci4])       : 0u;
                a[mi][3] = okh ? __float_as_uint(rb[512 + ci4]) : 0u;
            }
#pragma unroll
            for (int ni = 0; ni < 8; ++ni) {
                float2 bb = *(const float2*)(Bb +
                    ((((kf << 5) + (nw << 3) + ni) << 5) + lane) * 2);
                unsigned b0 = __float_as_uint(bb.x);
                unsigned b1 = __float_as_uint(bb.y);
                MMA_TF32(acc[0][ni], a[0], b0, b1);
                MMA_TF32(acc[1][ni], a[1], b0, b1);
            }
        }
        __syncthreads();    // all warps done reading BF[cur] before refill
        if (s + 2 < 18) {
            issueB(s + 2, cur);
            asm volatile("cp.async.commit_group;");
        }
    }

    // ---- epilogue --------------------------------------------------------
    if (MODE == 0) {
        const float* bias = xg_or_bias;
        float* ob = gout + ((size_t)img * NPIX + y0 * 64) * 256;
#pragma unroll
        for (int mi = 0; mi < 2; ++mi) {
#pragma unroll
            for (int ni = 0; ni < 8; ++ni) {
                int r0 = m_base + mi * 16 + g;
                int cl = n_base + ni * 8 + 2 * tg;
                float2 bb = *(const float2*)(bias + cl);
                float2 v0 = make_float2(acc[mi][ni][0] + bb.x, acc[mi][ni][1] + bb.y);
                float2 v1 = make_float2(acc[mi][ni][2] + bb.x, acc[mi][ni][3] + bb.y);
                *(float2*)(ob + (size_t)r0 * 256 + cl)       = v0;
                *(float2*)(ob + (size_t)(r0 + 8) * 256 + cl) = v1;
            }
        }
    } else {
        // exchange gates through smem (stride 264), then combine
        __syncthreads();
#pragma unroll
        for (int mi = 0; mi < 2; ++mi) {
#pragma unroll
            for (int ni = 0; ni < 8; ++ni) {
                int r0 = m_base + mi * 16 + g;
                int cl = n_base + ni * 8 + 2 * tg;
                *(float2*)(smf + r0 * 264 + cl) =
                    make_float2(acc[mi][ni][0], acc[mi][ni][1]);
                *(float2*)(smf + (r0 + 8) * 264 + cl) =
                    make_float2(acc[mi][ni][2], acc[mi][ni][3]);
            }
        }
        __syncthreads();
        int p = tid >> 2, f0 = (tid & 3) * 16;
        int pix = y0 * 64 + p;
        const float* xgp = xg_or_bias + ((size_t)(img * 10 + tstep) * NPIX + pix) * 256;
        float* cp = cbuf + ((size_t)img * NPIX + pix) * 64;
        float* hp = hout + ((size_t)img * NPIX + pix) * 64;
        float* op = outseq ? outseq + ((size_t)(img * 10 + tstep) * NPIX + pix) * 64
                           : (float*)0;
        const float* gm = smf + p * 264;
#pragma unroll
        for (int j = 0; j < 4; ++j) {
            int f = f0 + j * 4;
            float4 vi = *(const float4*)(gm + f);
            float4 vf = *(const float4*)(gm + 64 + f);
            float4 vg = *(const float4*)(gm + 128 + f);
            float4 vo = *(const float4*)(gm + 192 + f);
            float4 xi = *(const float4*)(xgp + f);
            float4 xf = *(const float4*)(xgp + 64 + f);
            float4 xgv = *(const float4*)(xgp + 128 + f);
            float4 xo = *(const float4*)(xgp + 192 + f);
            float4 co = *(const float4*)(cp + f);
            float4 cn, hn;
            cn.x = hsig(vf.x + xf.x) * co.x + hsig(vi.x + xi.x) * tanhf(vg.x + xgv.x);
            cn.y = hsig(vf.y + xf.y) * co.y + hsig(vi.y + xi.y) * tanhf(vg.y + xgv.y);
            cn.z = hsig(vf.z + xf.z) * co.z + hsig(vi.z + xi.z) * tanhf(vg.z + xgv.z);
            cn.w = hsig(vf.w + xf.w) * co.w + hsig(vi.w + xi.w) * tanhf(vg.w + xgv.w);
            hn.x = hsig(vo.x + xo.x) * tanhf(cn.x);
            hn.y = hsig(vo.y + xo.y) * tanhf(cn.y);
            hn.z = hsig(vo.z + xo.z) * tanhf(cn.z);
            hn.w = hsig(vo.w + xo.w) * tanhf(cn.w);
            *(float4*)(cp + f) = cn;
            *(float4*)(hp + f) = hn;
            if (op) *(float4*)(op + f) = hn;
        }
    }
}

// ---------------------------------------------------------------------------
extern "C" void kernel_launch(void* const* d_in, const int* in_sizes, int n_in,
                              void* d_out, int out_size) {
    const float* x   = (const float*)d_in[0];
    const float* Wx0 = (const float*)d_in[1];
    const float* Wh0 = (const float*)d_in[2];
    const float* b0  = (const float*)d_in[3];
    const float* Wx1 = (const float*)d_in[4];
    const float* Wh1 = (const float*)d_in[5];
    const float* b1  = (const float*)d_in[6];
    float* out = (float*)d_out;

    float *xg0, *xg1, *out0, *hbase, *cb, *wt;
    cudaGetSymbolAddress((void**)&xg0,   g_xg0);
    cudaGetSymbolAddress((void**)&xg1,   g_xg1);
    cudaGetSymbolAddress((void**)&out0,  g_out0);
    cudaGetSymbolAddress((void**)&hbase, g_h);
    cudaGetSymbolAddress((void**)&cb,    g_c);
    cudaGetSymbolAddress((void**)&wt,    g_wt);
    float* hb[2] = { hbase, hbase + SEG };

    cudaFuncSetAttribute(mm_conv<1>, cudaFuncAttributeMaxDynamicSharedMemorySize, SMEM_BYTES);
    cudaFuncSetAttribute(mm_conv<0>, cudaFuncAttributeMaxDynamicSharedMemorySize, SMEM_BYTES);

    // fragment-order tf32 weights: g_wt[0]=Wh0, [1]=Wx1, [2]=Wh1
    prep_w<<<864, 256>>>(Wh0, Wx1, Wh1);

    // Layer-0 input conv (exact fp32)
    conv_l0<<<dim3(16, 80), 256>>>(x, Wx0, b0, xg0);

    // Layer 0 recurrence
    zero_hc<<<2048, 1024>>>();
    for (int t = 0; t < 10; ++t)
        mm_conv<1><<<dim3(64, 8), 256, SMEM_BYTES>>>(
            hb[t & 1], wt, xg0, nullptr, cb, hb[(t + 1) & 1], out0, t);
    gather_out<<<2048, 1024>>>(out, 0);

    // Layer-1 batched input conv over 80 images
    mm_conv<0><<<dim3(64, 80), 256, SMEM_BYTES>>>(
        out0, wt + 576 * 256, b1, xg1, nullptr, nullptr, nullptr, 0);

    // Layer 1 recurrence
    zero_hc<<<2048, 1024>>>();
    for (int t = 0; t < 10; ++t)
        mm_conv<1><<<dim3(64, 8), 256, SMEM_BYTES>>>(
            hb[t & 1], wt + 2 * 576 * 256, xg1, nullptr, cb, hb[(t + 1) & 1], nullptr, t);
    gather_out<<<2048, 1024>>>(out, 1);

    (void)in_sizes; (void)n_in; (void)out_size;
}

// round 9
// speedup vs baseline: 1.6413x; 1.6413x over previous
#include <cuda_runtime.h>
#include <cuda_fp16.h>
#include <math.h>
#include <stdint.h>

// ---------------------------------------------------------------------------
// B=8, T=10, H=W=64, Cin=1, F=64, 4F=256, k=3x3 SAME.
// Output: [2][2][8][64][64][64] fp32.
// fp16 mma.sync (m16n8k16, fp32 accum) implicit-GEMM conv.
// Per block: M=64 positions (one image row) x N=256 gates, K=576 as 18 stages
// (9 taps x 2 chunks of 32 ch). A (3 h-rows, halo-padded fp16) persistent in
// smem; B pre-laid in fragment order (fp16 pairs) in gmem -> linear cp.async,
// ring-3 buffers, one barrier per stage.
// ---------------------------------------------------------------------------

#define HW    64
#define FDIM  64
#define C4    256
#define NPIX  4096
#define SEG   2097152            // 8*4096*64

__device__ float g_xg0[10 * 8 * NPIX * C4];
__device__ float g_xg1[10 * 8 * NPIX * C4];
__device__ float g_out0[10 * 8 * NPIX * FDIM];
__device__ float g_h[2][SEG];
__device__ float g_c[SEG];
// fp16 fragment-ordered weights: [which][s(18)][kf(2)][ct(32)][lane(32)] uint2
__device__ uint4 g_wtH[3 * 18 * 1024];

__device__ __forceinline__ float hsig(float x) {
    return fminf(fmaxf(0.2f * x + 0.5f, 0.0f), 1.0f);
}
__device__ __forceinline__ unsigned smem_u32(const void* p) {
    unsigned r;
    asm("{ .reg .u64 t; cvta.to.shared.u64 t, %1; cvt.u32.u64 %0, t; }"
        : "=r"(r) : "l"(p));
    return r;
}

#define MMA_F16(c, a, bx, by)                                                  \
    asm volatile("mma.sync.aligned.m16n8k16.row.col.f32.f16.f16.f32 "          \
        "{%0,%1,%2,%3}, {%4,%5,%6,%7}, {%8,%9}, {%0,%1,%2,%3};"                \
        : "+f"(c[0]), "+f"(c[1]), "+f"(c[2]), "+f"(c[3])                       \
        : "r"(a[0]), "r"(a[1]), "r"(a[2]), "r"(a[3]), "r"(bx), "r"(by))

// smem: A fp16x2 words [3][66][36] = 7128 u32 @0 (pos stride 36 words ->
// fragment banks 4g+tg conflict-free); B ring of 3 x 16KB @28672.
#define ABASEW 0
#define BBASEB 28672
#define SMEM_BYTES (28672 + 3 * 16384)    // 77824

// ---------------------------------------------------------------------------
__global__ void zero_hc() {
    int i = blockIdx.x * blockDim.x + threadIdx.x;
    if (i < SEG) { g_h[0][i] = 0.0f; g_c[i] = 0.0f; }
}
__global__ void gather_out(float* __restrict__ out, int layer) {
    int i = blockIdx.x * blockDim.x + threadIdx.x;
    if (i < SEG) {
        out[(size_t)layer * 2 * SEG + i]       = g_h[0][i];
        out[(size_t)layer * 2 * SEG + SEG + i] = g_c[i];
    }
}

// Rewrite weights into fp16 m16n8k16 B-fragment order:
// uint2[which][s][kf][ct][lane] = { pack(W[k0+2tg][n], W[k0+2tg+1][n]),
//                                   pack(W[k0+8+2tg][n], W[k0+9+2tg][n]) },
// k0 = s*32 + kf*16, n = ct*8 + g.
__global__ void prep_w(const float* __restrict__ w0, const float* __restrict__ w1,
                       const float* __restrict__ w2) {
    int idx = blockIdx.x * 256 + threadIdx.x;      // uint2 index
    if (idx >= 3 * 36864) return;
    int which = idx / 36864;
    int rem   = idx - which * 36864;
    int s  = rem >> 11;
    int r2 = rem & 2047;
    int kf = r2 >> 10;
    int ct = (r2 >> 5) & 31;
    int ln = r2 & 31;
    int tg = ln & 3, gg = ln >> 2;
    const float* src = (which == 0) ? w0 : (which == 1) ? w1 : w2;
    int k0  = s * 32 + kf * 16 + 2 * tg;
    int col = ct * 8 + gg;
    __half2 b0 = __floats2half2_rn(src[(size_t)k0 * 256 + col],
                                   src[(size_t)(k0 + 1) * 256 + col]);
    __half2 b1 = __floats2half2_rn(src[(size_t)(k0 + 8) * 256 + col],
                                   src[(size_t)(k0 + 9) * 256 + col]);
    uint2 v;
    v.x = *(unsigned*)&b0;
    v.y = *(unsigned*)&b1;
    ((uint2*)g_wtH)[idx] = v;
}

// Layer-0 input conv (Cin=1), exact fp32: xg0[img][pix][256] = b0 + conv(x, Wx0)
__global__ void conv_l0(const float* __restrict__ x, const float* __restrict__ w,
                        const float* __restrict__ b, float* __restrict__ xg) {
    __shared__ float ps[18 * 18];
    __shared__ float ws[9 * C4];
    int img = blockIdx.y;
    int by0 = (blockIdx.x >> 2) * 16, bx0 = (blockIdx.x & 3) * 16;
    int tid = threadIdx.x;
    for (int i = tid; i < 324; i += 256) {
        int ly = i / 18, lx = i - ly * 18;
        int gy = by0 + ly - 1, gx = bx0 + lx - 1;
        float v = 0.0f;
        if (gy >= 0 && gy < HW && gx >= 0 && gx < HW)
            v = x[(size_t)img * NPIX + gy * HW + gx];
        ps[i] = v;
    }
    for (int i = tid; i < 9 * C4; i += 256) ws[i] = w[i];
    __syncthreads();
    float wr[9];
#pragma unroll
    for (int tp = 0; tp < 9; ++tp) wr[tp] = ws[tp * C4 + tid];
    float bv = b[tid];
    for (int p = 0; p < 256; ++p) {
        int py = p >> 4, px = p & 15;
        float a = bv;
#pragma unroll
        for (int tp = 0; tp < 9; ++tp) {
            int dy = tp / 3, dx = tp - 3 * dy;
            a += ps[(py + dy) * 18 + (px + dx)] * wr[tp];
        }
        xg[((size_t)img * NPIX + (by0 + py) * HW + (bx0 + px)) * C4 + tid] = a;
    }
}

// ---------------------------------------------------------------------------
// fp16 mma.sync conv block. MODE 1: LSTM step; MODE 0: gates = conv + bias.
// 8 warps as 2(M) x 4(N); warp tile 32x64; 64 fp32 accumulators per thread.
// ---------------------------------------------------------------------------
template <int MODE>
__global__ void __launch_bounds__(256, 2)
mm_conv(const float* __restrict__ in, const uint2* __restrict__ wt,
        const float* __restrict__ xg_or_bias, float* __restrict__ gout,
        float* __restrict__ cbuf, float* __restrict__ hout,
        float* __restrict__ outseq, int tstep) {
    extern __shared__ float smf[];
    unsigned* Au = (unsigned*)smf;                 // A fp16x2 words
    unsigned sbase = smem_u32(smf);
    int tid = threadIdx.x;
    int wid = tid >> 5, lane = tid & 31;
    int g = lane >> 2, tg = lane & 3;
    int mw = wid >> 2, nw = wid & 3;
    int m_base = mw * 32, n_base = nw * 64;
    int img = blockIdx.y;
    int y0 = blockIdx.x;                       // image row handled by block
    const float* inb = in + (size_t)img * (NPIX * FDIM);

    // ---- fill persistent A: [3][66 pos][32 ch-pairs], fp16x2, halo-padded --
    for (int i = tid; i < 6336; i += 256) {        // 3*66*32 words
        int dyi = i / 2112;
        int rem = i - dyi * 2112;
        int xx = rem >> 5;                         // 0..65  (pos = x+1)
        int cp = rem & 31;                         // channel pair
        int y = y0 + dyi - 1;
        int x = xx - 1;
        unsigned w = 0u;
        if ((unsigned)y < 64u && (unsigned)x < 64u) {
            float2 v = *(const float2*)(inb + (size_t)(((y << 6) + x) * 64 + cp * 2));
            __half2 h2 = __floats2half2_rn(v.x, v.y);
            w = *(unsigned*)&h2;
        }
        Au[dyi * 2376 + xx * 36 + cp] = w;
    }

    float acc[2][8][4];
#pragma unroll
    for (int mi = 0; mi < 2; ++mi)
#pragma unroll
        for (int ni = 0; ni < 8; ++ni)
#pragma unroll
            for (int r = 0; r < 4; ++r) acc[mi][ni][r] = 0.0f;

    auto issueB = [&](int s, int buf) {
        const uint4* wp = (const uint4*)(wt + (size_t)s * 2048);
        unsigned dbase = sbase + (unsigned)(BBASEB + buf * 16384);
#pragma unroll
        for (int i = 0; i < 4; ++i) {
            int idx = tid + i * 256;               // 0..1023 (16B chunks)
            unsigned daddr = dbase + (unsigned)idx * 16;
            asm volatile("cp.async.ca.shared.global [%0], [%1], 16;"
                         :: "r"(daddr), "l"(wp + idx));
        }
    };

    issueB(0, 0);
    asm volatile("cp.async.commit_group;");
    issueB(1, 1);
    asm volatile("cp.async.commit_group;");

    for (int s = 0; s < 18; ++s) {
        if (s < 17) asm volatile("cp.async.wait_group 1;");
        else        asm volatile("cp.async.wait_group 0;");
        __syncthreads();           // B(s) visible; A ready (s=0); s-1 compute done
        if (s + 2 < 18) {
            issueB(s + 2, (s + 2) % 3);            // overwrites (s-1)%3: safe
            asm volatile("cp.async.commit_group;");
        }

        int tap = s >> 1;
        int qy = tap / 3;
        int dx = tap - 3 * qy - 1;
        int wch = (s & 1) << 4;                    // channel-pair word offset
        const uint2* Bb = (const uint2*)((char*)smf + BBASEB + (s % 3) * 16384);
        int pl0 = m_base + g + dx + 1;             // halo: always in [0,66)
        const unsigned* Ad = Au + qy * 2376;

#pragma unroll
        for (int kf = 0; kf < 2; ++kf) {
            int w0 = wch + kf * 8 + tg;
            unsigned a[2][4];
#pragma unroll
            for (int mi = 0; mi < 2; ++mi) {
                const unsigned* rb = Ad + (pl0 + mi * 16) * 36;
                a[mi][0] = rb[w0];
                a[mi][1] = rb[8 * 36 + w0];
                a[mi][2] = rb[w0 + 4];
                a[mi][3] = rb[8 * 36 + w0 + 4];
            }
#pragma unroll
            for (int ni = 0; ni < 8; ++ni) {
                uint2 bb = Bb[((kf << 5) + (nw << 3) + ni) * 32 + lane];
                MMA_F16(acc[0][ni], a[0], bb.x, bb.y);
                MMA_F16(acc[1][ni], a[1], bb.x, bb.y);
            }
        }
    }

    // ---- epilogue --------------------------------------------------------
    if (MODE == 0) {
        const float* bias = xg_or_bias;
        float* ob = gout + ((size_t)img * NPIX + y0 * 64) * 256;
#pragma unroll
        for (int mi = 0; mi < 2; ++mi) {
#pragma unroll
            for (int ni = 0; ni < 8; ++ni) {
                int r0 = m_base + mi * 16 + g;
                int cl = n_base + ni * 8 + 2 * tg;
                float2 bb = *(const float2*)(bias + cl);
                float2 v0 = make_float2(acc[mi][ni][0] + bb.x, acc[mi][ni][1] + bb.y);
                float2 v1 = make_float2(acc[mi][ni][2] + bb.x, acc[mi][ni][3] + bb.y);
                *(float2*)(ob + (size_t)r0 * 256 + cl)       = v0;
                *(float2*)(ob + (size_t)(r0 + 8) * 256 + cl) = v1;
            }
        }
    } else {
        // exchange gates through smem (stride 264), then combine
        __syncthreads();
#pragma unroll
        for (int mi = 0; mi < 2; ++mi) {
#pragma unroll
            for (int ni = 0; ni < 8; ++ni) {
                int r0 = m_base + mi * 16 + g;
                int cl = n_base + ni * 8 + 2 * tg;
                *(float2*)(smf + r0 * 264 + cl) =
                    make_float2(acc[mi][ni][0], acc[mi][ni][1]);
                *(float2*)(smf + (r0 + 8) * 264 + cl) =
                    make_float2(acc[mi][ni][2], acc[mi][ni][3]);
            }
        }
        __syncthreads();
        int p = tid >> 2, f0 = (tid & 3) * 16;
        int pix = y0 * 64 + p;
        const float* xgp = xg_or_bias + ((size_t)(img * 10 + tstep) * NPIX + pix) * 256;
        float* cp = cbuf + ((size_t)img * NPIX + pix) * 64;
        float* hp = hout + ((size_t)img * NPIX + pix) * 64;
        float* op = outseq ? outseq + ((size_t)(img * 10 + tstep) * NPIX + pix) * 64
                           : (float*)0;
        const float* gm = smf + p * 264;
#pragma unroll
        for (int j = 0; j < 4; ++j) {
            int f = f0 + j * 4;
            float4 vi = *(const float4*)(gm + f);
            float4 vf = *(const float4*)(gm + 64 + f);
            float4 vg = *(const float4*)(gm + 128 + f);
            float4 vo = *(const float4*)(gm + 192 + f);
            float4 xi = *(const float4*)(xgp + f);
            float4 xf = *(const float4*)(xgp + 64 + f);
            float4 xgv = *(const float4*)(xgp + 128 + f);
            float4 xo = *(const float4*)(xgp + 192 + f);
            float4 co = *(const float4*)(cp + f);
            float4 cn, hn;
            cn.x = hsig(vf.x + xf.x) * co.x + hsig(vi.x + xi.x) * tanhf(vg.x + xgv.x);
            cn.y = hsig(vf.y + xf.y) * co.y + hsig(vi.y + xi.y) * tanhf(vg.y + xgv.y);
            cn.z = hsig(vf.z + xf.z) * co.z + hsig(vi.z + xi.z) * tanhf(vg.z + xgv.z);
            cn.w = hsig(vf.w + xf.w) * co.w + hsig(vi.w + xi.w) * tanhf(vg.w + xgv.w);
            hn.x = hsig(vo.x + xo.x) * tanhf(cn.x);
            hn.y = hsig(vo.y + xo.y) * tanhf(cn.y);
            hn.z = hsig(vo.z + xo.z) * tanhf(cn.z);
            hn.w = hsig(vo.w + xo.w) * tanhf(cn.w);
            *(float4*)(cp + f) = cn;
            *(float4*)(hp + f) = hn;
            if (op) *(float4*)(op + f) = hn;
        }
    }
}

// ---------------------------------------------------------------------------
extern "C" void kernel_launch(void* const* d_in, const int* in_sizes, int n_in,
                              void* d_out, int out_size) {
    const float* x   = (const float*)d_in[0];
    const float* Wx0 = (const float*)d_in[1];
    const float* Wh0 = (const float*)d_in[2];
    const float* b0  = (const float*)d_in[3];
    const float* Wx1 = (const float*)d_in[4];
    const float* Wh1 = (const float*)d_in[5];
    const float* b1  = (const float*)d_in[6];
    float* out = (float*)d_out;

    float *xg0, *xg1, *out0, *hbase, *cb;
    uint2* wt;
    cudaGetSymbolAddress((void**)&xg0,   g_xg0);
    cudaGetSymbolAddress((void**)&xg1,   g_xg1);
    cudaGetSymbolAddress((void**)&out0,  g_out0);
    cudaGetSymbolAddress((void**)&hbase, g_h);
    cudaGetSymbolAddress((void**)&cb,    g_c);
    cudaGetSymbolAddress((void**)&wt,    g_wtH);
    float* hb[2] = { hbase, hbase + SEG };

    cudaFuncSetAttribute(mm_conv<1>, cudaFuncAttributeMaxDynamicSharedMemorySize, SMEM_BYTES);
    cudaFuncSetAttribute(mm_conv<0>, cudaFuncAttributeMaxDynamicSharedMemorySize, SMEM_BYTES);

    // fp16 fragment-order weights: [0]=Wh0, [1]=Wx1, [2]=Wh1
    prep_w<<<432, 256>>>(Wh0, Wx1, Wh1);

    // Layer-0 input conv (exact fp32)
    conv_l0<<<dim3(16, 80), 256>>>(x, Wx0, b0, xg0);

    // Layer 0 recurrence
    zero_hc<<<2048, 1024>>>();
    for (int t = 0; t < 10; ++t)
        mm_conv<1><<<dim3(64, 8), 256, SMEM_BYTES>>>(
            hb[t & 1], wt, xg0, nullptr, cb, hb[(t + 1) & 1], out0, t);
    gather_out<<<2048, 1024>>>(out, 0);

    // Layer-1 batched input conv over 80 images
    mm_conv<0><<<dim3(64, 80), 256, SMEM_BYTES>>>(
        out0, wt + 36864, b1, xg1, nullptr, nullptr, nullptr, 0);

    // Layer 1 recurrence
    zero_hc<<<2048, 1024>>>();
    for (int t = 0; t < 10; ++t)
        mm_conv<1><<<dim3(64, 8), 256, SMEM_BYTES>>>(
            hb[t & 1], wt + 2 * 36864, xg1, nullptr, cb, hb[(t + 1) & 1], nullptr, t);
    gather_out<<<2048, 1024>>>(out, 1);

    (void)in_sizes; (void)n_in; (void)out_size;
}

// round 10
// speedup vs baseline: 1.8332x; 1.1169x over previous
#include <cuda_runtime.h>
#include <cuda_fp16.h>
#include <math.h>
#include <stdint.h>

// ---------------------------------------------------------------------------
// B=8, T=10, H=W=64, Cin=1, F=64, 4F=256, k=3x3 SAME.
// Output: [2][2][8][64][64][64] fp32.
// fp16 mma.sync (m16n8k16, fp32 accum) implicit-GEMM conv.
// Per block: M=64 positions (one image row) x N=256 gates, K=576 as 9 stages
// (one 3x3 tap each, 64 ch). A (3 h-rows, halo-padded fp16) persistent in
// smem, fragments via ldmatrix.x4; B pre-laid in fragment order in gmem ->
// linear cp.async, ring-2 32KB buffers. t=0 steps replaced by exact
// elementwise init (h=0 -> gates = xg).
// ---------------------------------------------------------------------------

#define HW    64
#define FDIM  64
#define C4    256
#define NPIX  4096
#define SEG   2097152            // 8*4096*64

__device__ float g_xg0[10 * 8 * NPIX * C4];
__device__ float g_xg1[10 * 8 * NPIX * C4];
__device__ float g_out0[10 * 8 * NPIX * FDIM];
__device__ float g_h[2][SEG];
__device__ float g_c[SEG];
// fp16 fragment-ordered weights: [which][tap(9)][kf(4)][ct(32)][lane(32)] uint2
__device__ uint4 g_wtH[3 * 18 * 1024];

__device__ __forceinline__ float hsig(float x) {
    return fminf(fmaxf(0.2f * x + 0.5f, 0.0f), 1.0f);
}
__device__ __forceinline__ unsigned smem_u32(const void* p) {
    unsigned r;
    asm("{ .reg .u64 t; cvta.to.shared.u64 t, %1; cvt.u32.u64 %0, t; }"
        : "=r"(r) : "l"(p));
    return r;
}
__device__ __forceinline__ void ldm_x4(unsigned* a, unsigned addr) {
    asm volatile("ldmatrix.sync.aligned.m8n8.x4.shared.b16 {%0,%1,%2,%3}, [%4];"
        : "=r"(a[0]), "=r"(a[1]), "=r"(a[2]), "=r"(a[3]) : "r"(addr));
}

#define MMA_F16(c, a, bx, by)                                                  \
    asm volatile("mma.sync.aligned.m16n8k16.row.col.f32.f16.f16.f32 "          \
        "{%0,%1,%2,%3}, {%4,%5,%6,%7}, {%8,%9}, {%0,%1,%2,%3};"                \
        : "+f"(c[0]), "+f"(c[1]), "+f"(c[2]), "+f"(c[3])                       \
        : "r"(a[0]), "r"(a[1]), "r"(a[2]), "r"(a[3]), "r"(bx), "r"(by))

// smem: A fp16x2 words [3][66][36] = 7128 u32 @0 (pos stride 36 words);
// B ring of 2 x 32KB @28672.
#define BBASEB 28672
#define SMEM_BYTES (28672 + 2 * 32768)    // 94208 -> 2 blocks/SM

// ---------------------------------------------------------------------------
__global__ void gather_out(float* __restrict__ out, int layer) {
    int i = blockIdx.x * blockDim.x + threadIdx.x;
    if (i < SEG) {
        out[(size_t)layer * 2 * SEG + i]       = g_h[0][i];
        out[(size_t)layer * 2 * SEG + SEG + i] = g_c[i];
    }
}

// t=0 LSTM step, exact: h_prev = 0 -> gates = xg precisely.
// c = hs(i)*tanh(g); h = hs(o)*tanh(c). f-gate unused (c_prev = 0).
__global__ void lstm_init(const float* __restrict__ xg, float* __restrict__ cbuf,
                          float* __restrict__ hout, float* __restrict__ outseq) {
    int i = blockIdx.x * blockDim.x + threadIdx.x;     // float4 index
    if (i >= SEG / 4) return;
    int f4 = (i & 15) << 2;
    int pixg = i >> 4;                                  // img*4096 + pix
    int img = pixg >> 12;
    const float* xp = xg + ((size_t)(img * 10) * NPIX + (pixg & 4095)) * 256 + f4;
    float4 ig = *(const float4*)(xp);
    float4 gg = *(const float4*)(xp + 128);
    float4 og = *(const float4*)(xp + 192);
    float4 cn, hn;
    cn.x = hsig(ig.x) * tanhf(gg.x);
    cn.y = hsig(ig.y) * tanhf(gg.y);
    cn.z = hsig(ig.z) * tanhf(gg.z);
    cn.w = hsig(ig.w) * tanhf(gg.w);
    hn.x = hsig(og.x) * tanhf(cn.x);
    hn.y = hsig(og.y) * tanhf(cn.y);
    hn.z = hsig(og.z) * tanhf(cn.z);
    hn.w = hsig(og.w) * tanhf(cn.w);
    *(float4*)(cbuf + (size_t)i * 4) = cn;
    *(float4*)(hout + (size_t)i * 4) = hn;
    if (outseq)
        *(float4*)(outseq + ((size_t)(img * 10) * NPIX + (pixg & 4095)) * 64 + f4) = hn;
}

// Rewrite weights into fp16 m16n8k16 B-fragment order, K=64 stages:
// uint2[which][tap][kf][ct][lane] = { pack(W[k0+2tg][n], W[k0+2tg+1][n]),
//                                     pack(W[k0+8+2tg][n], W[k0+9+2tg][n]) },
// k0 = tap*64 + kf*16, n = ct*8 + g.
__global__ void prep_w(const float* __restrict__ w0, const float* __restrict__ w1,
                       const float* __restrict__ w2) {
    int idx = blockIdx.x * 256 + threadIdx.x;      // uint2 index
    if (idx >= 3 * 36864) return;
    int which = idx / 36864;
    int rem   = idx - which * 36864;
    int tap = rem >> 12;
    int r2  = rem & 4095;
    int kf = r2 >> 10;
    int ct = (r2 >> 5) & 31;
    int ln = r2 & 31;
    int tg = ln & 3, gg = ln >> 2;
    const float* src = (which == 0) ? w0 : (which == 1) ? w1 : w2;
    int k0  = tap * 64 + kf * 16 + 2 * tg;
    int col = ct * 8 + gg;
    __half2 b0 = __floats2half2_rn(src[(size_t)k0 * 256 + col],
                                   src[(size_t)(k0 + 1) * 256 + col]);
    __half2 b1 = __floats2half2_rn(src[(size_t)(k0 + 8) * 256 + col],
                                   src[(size_t)(k0 + 9) * 256 + col]);
    uint2 v;
    v.x = *(unsigned*)&b0;
    v.y = *(unsigned*)&b1;
    ((uint2*)g_wtH)[idx] = v;
}

// Layer-0 input conv (Cin=1), exact fp32: xg0[img][pix][256] = b0 + conv(x, Wx0)
__global__ void conv_l0(const float* __restrict__ x, const float* __restrict__ w,
                        const float* __restrict__ b, float* __restrict__ xg) {
    __shared__ float ps[18 * 18];
    __shared__ float ws[9 * C4];
    int img = blockIdx.y;
    int by0 = (blockIdx.x >> 2) * 16, bx0 = (blockIdx.x & 3) * 16;
    int tid = threadIdx.x;
    for (int i = tid; i < 324; i += 256) {
        int ly = i / 18, lx = i - ly * 18;
        int gy = by0 + ly - 1, gx = bx0 + lx - 1;
        float v = 0.0f;
        if (gy >= 0 && gy < HW && gx >= 0 && gx < HW)
            v = x[(size_t)img * NPIX + gy * HW + gx];
        ps[i] = v;
    }
    for (int i = tid; i < 9 * C4; i += 256) ws[i] = w[i];
    __syncthreads();
    float wr[9];
#pragma unroll
    for (int tp = 0; tp < 9; ++tp) wr[tp] = ws[tp * C4 + tid];
    float bv = b[tid];
    for (int p = 0; p < 256; ++p) {
        int py = p >> 4, px = p & 15;
        float a = bv;
#pragma unroll
        for (int tp = 0; tp < 9; ++tp) {
            int dy = tp / 3, dx = tp - 3 * dy;
            a += ps[(py + dy) * 18 + (px + dx)] * wr[tp];
        }
        xg[((size_t)img * NPIX + (by0 + py) * HW + (bx0 + px)) * C4 + tid] = a;
    }
}

// ---------------------------------------------------------------------------
// fp16 mma.sync conv block. MODE 1: LSTM step; MODE 0: gates = conv + bias.
// 8 warps as 2(M) x 4(N); warp tile 32x64; 64 fp32 accumulators per thread.
// ---------------------------------------------------------------------------
template <int MODE>
__global__ void __launch_bounds__(256, 2)
mm_conv(const float* __restrict__ in, const uint2* __restrict__ wt,
        const float* __restrict__ xg_or_bias, float* __restrict__ gout,
        float* __restrict__ cbuf, float* __restrict__ hout,
        float* __restrict__ outseq, int tstep) {
    extern __shared__ float smf[];
    unsigned* Au = (unsigned*)smf;                 // A fp16x2 words
    unsigned sbase = smem_u32(smf);
    int tid = threadIdx.x;
    int wid = tid >> 5, lane = tid & 31;
    int g = lane >> 2, tg = lane & 3;
    int mw = wid >> 2, nw = wid & 3;
    int m_base = mw * 32, n_base = nw * 64;
    int img = blockIdx.y;
    int y0 = blockIdx.x;                       // image row handled by block
    const float* inb = in + (size_t)img * (NPIX * FDIM);
    // per-lane invariant part of ldmatrix addresses (words)
    int lanepart = (lane & 15) * 36 + ((lane >> 4) << 2);

    // ---- fill persistent A: [3][66 pos][32 ch-pairs], fp16x2, halo-padded --
    for (int i = tid; i < 6336; i += 256) {        // 3*66*32 words
        int dyi = i / 2112;
        int rem = i - dyi * 2112;
        int xx = rem >> 5;                         // 0..65  (pos = x+1)
        int cp = rem & 31;                         // channel pair
        int y = y0 + dyi - 1;
        int x = xx - 1;
        unsigned w = 0u;
        if ((unsigned)y < 64u && (unsigned)x < 64u) {
            float2 v = *(const float2*)(inb + (size_t)(((y << 6) + x) * 64 + cp * 2));
            __half2 h2 = __floats2half2_rn(v.x, v.y);
            w = *(unsigned*)&h2;
        }
        Au[dyi * 2376 + xx * 36 + cp] = w;
    }

    float acc[2][8][4];
#pragma unroll
    for (int mi = 0; mi < 2; ++mi)
#pragma unroll
        for (int ni = 0; ni < 8; ++ni)
#pragma unroll
            for (int r = 0; r < 4; ++r) acc[mi][ni][r] = 0.0f;

    auto issueB = [&](int s, int buf) {
        const uint4* wp = (const uint4*)(wt + (size_t)s * 4096);
        unsigned dbase = sbase + (unsigned)(BBASEB + buf * 32768);
#pragma unroll
        for (int i = 0; i < 8; ++i) {
            int idx = tid + i * 256;               // 0..2047 (16B chunks)
            unsigned daddr = dbase + (unsigned)idx * 16;
            asm volatile("cp.async.ca.shared.global [%0], [%1], 16;"
                         :: "r"(daddr), "l"(wp + idx));
        }
    };

    issueB(0, 0);
    asm volatile("cp.async.commit_group;");
    issueB(1, 1);
    asm volatile("cp.async.commit_group;");

    for (int s = 0; s < 9; ++s) {
        if (s < 8) asm volatile("cp.async.wait_group 1;");
        else       asm volatile("cp.async.wait_group 0;");
        __syncthreads();       // B(s) visible; A ready (s=0)

        int qy = s / 3;                            // dy+1
        int dx = s - 3 * qy - 1;
        const uint2* Bb = (const uint2*)((char*)smf + BBASEB + (s & 1) * 32768);
        // word base of this stage's A rows for this warp (mi=0)
        int rowbase = qy * 2376 + (m_base + dx + 1) * 36 + lanepart;
        unsigned aaddr0 = sbase + (unsigned)rowbase * 4;
        unsigned aaddr1 = aaddr0 + 16 * 36 * 4;

#pragma unroll
        for (int kf = 0; kf < 4; ++kf) {
            unsigned a0[4], a1[4];
            ldm_x4(a0, aaddr0 + (unsigned)(kf * 8) * 4);
            ldm_x4(a1, aaddr1 + (unsigned)(kf * 8) * 4);
            const uint2* bp = Bb + ((kf << 5) + (nw << 3)) * 32 + lane;
#pragma unroll
            for (int h = 0; h < 2; ++h) {
                uint2 bb[4];
#pragma unroll
                for (int j = 0; j < 4; ++j) bb[j] = bp[(h * 4 + j) * 32];
#pragma unroll
                for (int j = 0; j < 4; ++j) {
                    MMA_F16(acc[0][h * 4 + j], a0, bb[j].x, bb[j].y);
                    MMA_F16(acc[1][h * 4 + j], a1, bb[j].x, bb[j].y);
                }
            }
        }
        __syncthreads();       // all warps done with BF[s&1] before refill
        if (s + 2 < 9) {
            issueB(s + 2, s & 1);
            asm volatile("cp.async.commit_group;");
        }
    }

    // ---- epilogue --------------------------------------------------------
    if (MODE == 0) {
        const float* bias = xg_or_bias;
        float* ob = gout + ((size_t)img * NPIX + y0 * 64) * 256;
#pragma unroll
        for (int mi = 0; mi < 2; ++mi) {
#pragma unroll
            for (int ni = 0; ni < 8; ++ni) {
                int r0 = m_base + mi * 16 + g;
                int cl = n_base + ni * 8 + 2 * tg;
                float2 bb = *(const float2*)(bias + cl);
                float2 v0 = make_float2(acc[mi][ni][0] + bb.x, acc[mi][ni][1] + bb.y);
                float2 v1 = make_float2(acc[mi][ni][2] + bb.x, acc[mi][ni][3] + bb.y);
                *(float2*)(ob + (size_t)r0 * 256 + cl)       = v0;
                *(float2*)(ob + (size_t)(r0 + 8) * 256 + cl) = v1;
            }
        }
    } else {
        // exchange gates through smem (stride 264), then combine
        __syncthreads();
#pragma unroll
        for (int mi = 0; mi < 2; ++mi) {
#pragma unroll
            for (int ni = 0; ni < 8; ++ni) {
                int r0 = m_base + mi * 16 + g;
                int cl = n_base + ni * 8 + 2 * tg;
                *(float2*)(smf + r0 * 264 + cl) =
                    make_float2(acc[mi][ni][0], acc[mi][ni][1]);
                *(float2*)(smf + (r0 + 8) * 264 + cl) =
                    make_float2(acc[mi][ni][2], acc[mi][ni][3]);
            }
        }
        __syncthreads();
        int p = tid >> 2, f0 = (tid & 3) * 16;
        int pix = y0 * 64 + p;
        const float* xgp = xg_or_bias + ((size_t)(img * 10 + tstep) * NPIX + pix) * 256;
        float* cp = cbuf + ((size_t)img * NPIX + pix) * 64;
        float* hp = hout + ((size_t)img * NPIX + pix) * 64;
        float* op = outseq ? outseq + ((size_t)(img * 10 + tstep) * NPIX + pix) * 64
                           : (float*)0;
        const float* gm = smf + p * 264;
#pragma unroll
        for (int j = 0; j < 4; ++j) {
            int f = f0 + j * 4;
            float4 vi = *(const float4*)(gm + f);
            float4 vf = *(const float4*)(gm + 64 + f);
            float4 vg = *(const float4*)(gm + 128 + f);
            float4 vo = *(const float4*)(gm + 192 + f);
            float4 xi = *(const float4*)(xgp + f);
            float4 xf = *(const float4*)(xgp + 64 + f);
            float4 xgv = *(const float4*)(xgp + 128 + f);
            float4 xo = *(const float4*)(xgp + 192 + f);
            float4 co = *(const float4*)(cp + f);
            float4 cn, hn;
            cn.x = hsig(vf.x + xf.x) * co.x + hsig(vi.x + xi.x) * tanhf(vg.x + xgv.x);
            cn.y = hsig(vf.y + xf.y) * co.y + hsig(vi.y + xi.y) * tanhf(vg.y + xgv.y);
            cn.z = hsig(vf.z + xf.z) * co.z + hsig(vi.z + xi.z) * tanhf(vg.z + xgv.z);
            cn.w = hsig(vf.w + xf.w) * co.w + hsig(vi.w + xi.w) * tanhf(vg.w + xgv.w);
            hn.x = hsig(vo.x + xo.x) * tanhf(cn.x);
            hn.y = hsig(vo.y + xo.y) * tanhf(cn.y);
            hn.z = hsig(vo.z + xo.z) * tanhf(cn.z);
            hn.w = hsig(vo.w + xo.w) * tanhf(cn.w);
            *(float4*)(cp + f) = cn;
            *(float4*)(hp + f) = hn;
            if (op) *(float4*)(op + f) = hn;
        }
    }
}

// ---------------------------------------------------------------------------
extern "C" void kernel_launch(void* const* d_in, const int* in_sizes, int n_in,
                              void* d_out, int out_size) {
    const float* x   = (const float*)d_in[0];
    const float* Wx0 = (const float*)d_in[1];
    const float* Wh0 = (const float*)d_in[2];
    const float* b0  = (const float*)d_in[3];
    const float* Wx1 = (const float*)d_in[4];
    const float* Wh1 = (const float*)d_in[5];
    const float* b1  = (const float*)d_in[6];
    float* out = (float*)d_out;

    float *xg0, *xg1, *out0, *hbase, *cb;
    uint2* wt;
    cudaGetSymbolAddress((void**)&xg0,   g_xg0);
    cudaGetSymbolAddress((void**)&xg1,   g_xg1);
    cudaGetSymbolAddress((void**)&out0,  g_out0);
    cudaGetSymbolAddress((void**)&hbase, g_h);
    cudaGetSymbolAddress((void**)&cb,    g_c);
    cudaGetSymbolAddress((void**)&wt,    g_wtH);
    float* hb[2] = { hbase, hbase + SEG };

    cudaFuncSetAttribute(mm_conv<1>, cudaFuncAttributeMaxDynamicSharedMemorySize, SMEM_BYTES);
    cudaFuncSetAttribute(mm_conv<0>, cudaFuncAttributeMaxDynamicSharedMemorySize, SMEM_BYTES);

    // fp16 fragment-order weights: [0]=Wh0, [1]=Wx1, [2]=Wh1
    prep_w<<<432, 256>>>(Wh0, Wx1, Wh1);

    // Layer-0 input conv (exact fp32)
    conv_l0<<<dim3(16, 80), 256>>>(x, Wx0, b0, xg0);

    // Layer 0: t=0 exact init, then t=1..9 conv steps
    lstm_init<<<2048, 256>>>(xg0, cb, hb[1], out0);
    for (int t = 1; t < 10; ++t)
        mm_conv<1><<<dim3(64, 8), 256, SMEM_BYTES>>>(
            hb[t & 1], wt, xg0, nullptr, cb, hb[(t + 1) & 1], out0, t);
    gather_out<<<2048, 1024>>>(out, 0);

    // Layer-1 batched input conv over 80 images
    mm_conv<0><<<dim3(64, 80), 256, SMEM_BYTES>>>(
        out0, wt + 36864, b1, xg1, nullptr, nullptr, nullptr, 0);

    // Layer 1: t=0 exact init, then t=1..9 conv steps
    lstm_init<<<2048, 256>>>(xg1, cb, hb[1], nullptr);
    for (int t = 1; t < 10; ++t)
        mm_conv<1><<<dim3(64, 8), 256, SMEM_BYTES>>>(
            hb[t & 1], wt + 2 * 36864, xg1, nullptr, cb, hb[(t + 1) & 1], nullptr, t);
    gather_out<<<2048, 1024>>>(out, 1);

    (void)in_sizes; (void)n_in; (void)out_size;
}

// round 11
// speedup vs baseline: 1.9154x; 1.0448x over previous
#include <cuda_runtime.h>
#include <cuda_fp16.h>
#include <math.h>
#include <stdint.h>

// ---------------------------------------------------------------------------
// B=8, T=10, H=W=64, Cin=1, F=64, 4F=256, k=3x3 SAME.
// Output: [2][2][8][64][64][64] fp32.
// fp16 mma.sync (m16n8k16, fp32 accum) implicit-GEMM conv.
// Per block: M=64 positions (one image row) x N=128 (one channel-half, all 4
// gates interleaved), K=576 as 9 taps. Warp tile 32x32 -> 32 accums ->
// 3 blocks/SM. Gate-interleaved columns => epilogue is sync-free (each thread
// holds i,f,g,o for its (pos,ch) pairs). xg stored gate-minor [pix][f][4].
// ---------------------------------------------------------------------------

#define HW    64
#define FDIM  64
#define C4    256
#define NPIX  4096
#define SEG   2097152            // 8*4096*64

__device__ float g_xg0[10 * 8 * NPIX * C4];   // gate-minor: [timg][pix][f][4]
__device__ float g_xg1[10 * 8 * NPIX * C4];
__device__ float g_out0[10 * 8 * NPIX * FDIM];
__device__ float g_h[2][SEG];
__device__ float g_c[SEG];
// fp16 fragment-ordered weights:
// uint2[which(3)][half(2)][tap(9)][kf(4)][ctb(16)][lane(32)]
__device__ uint2 g_wtH[3 * 2 * 9 * 4 * 16 * 32];

__device__ __forceinline__ float hsig(float x) {
    return fminf(fmaxf(0.2f * x + 0.5f, 0.0f), 1.0f);
}
__device__ __forceinline__ unsigned smem_u32(const void* p) {
    unsigned r;
    asm("{ .reg .u64 t; cvta.to.shared.u64 t, %1; cvt.u32.u64 %0, t; }"
        : "=r"(r) : "l"(p));
    return r;
}
__device__ __forceinline__ void ldm_x4(unsigned* a, unsigned addr) {
    asm volatile("ldmatrix.sync.aligned.m8n8.x4.shared.b16 {%0,%1,%2,%3}, [%4];"
        : "=r"(a[0]), "=r"(a[1]), "=r"(a[2]), "=r"(a[3]) : "r"(addr));
}

#define MMA_F16(c, a, bx, by)                                                  \
    asm volatile("mma.sync.aligned.m16n8k16.row.col.f32.f16.f16.f32 "          \
        "{%0,%1,%2,%3}, {%4,%5,%6,%7}, {%8,%9}, {%0,%1,%2,%3};"                \
        : "+f"(c[0]), "+f"(c[1]), "+f"(c[2]), "+f"(c[3])                       \
        : "r"(a[0]), "r"(a[1]), "r"(a[2]), "r"(a[3]), "r"(bx), "r"(by))

// smem: A fp16x2 words [3][66][36] = 7128 u32 @0 (pos stride 36 words);
// B ring of 2 x 16KB @28672. Total 61440B -> 3 blocks/SM.
#define BBASEB 28672
#define SMEM_BYTES (28672 + 2 * 16384)

// ---------------------------------------------------------------------------
__global__ void gather_out(float* __restrict__ out, int layer) {
    int i = blockIdx.x * blockDim.x + threadIdx.x;
    if (i < SEG) {
        out[(size_t)layer * 2 * SEG + i]       = g_h[0][i];
        out[(size_t)layer * 2 * SEG + SEG + i] = g_c[i];
    }
}

// t=0 LSTM step, exact (h_prev=0 -> gates = xg). xg is gate-minor [pix][f][4].
__global__ void lstm_init(const float* __restrict__ xg, float* __restrict__ cbuf,
                          float* __restrict__ hout, float* __restrict__ outseq) {
    int i = blockIdx.x * blockDim.x + threadIdx.x;     // float4 index in [pix][64]
    if (i >= SEG / 4) return;
    int f4 = (i & 15) << 2;                             // channel base
    int pixg = i >> 4;                                  // img*4096 + pix
    int img = pixg >> 12;
    const float4* xp = (const float4*)(xg +
        ((size_t)(img * 10) * NPIX + (pixg & 4095)) * 256 + (size_t)f4 * 4);
    float4 cn, hn;
    {
        float4 q0 = xp[0], q1 = xp[1], q2 = xp[2], q3 = xp[3];  // (i,f,g,o) x 4 ch
        cn.x = hsig(q0.x) * tanhf(q0.z);
        cn.y = hsig(q1.x) * tanhf(q1.z);
        cn.z = hsig(q2.x) * tanhf(q2.z);
        cn.w = hsig(q3.x) * tanhf(q3.z);
        hn.x = hsig(q0.w) * tanhf(cn.x);
        hn.y = hsig(q1.w) * tanhf(cn.y);
        hn.z = hsig(q2.w) * tanhf(cn.z);
        hn.w = hsig(q3.w) * tanhf(cn.w);
    }
    *(float4*)(cbuf + (size_t)i * 4) = cn;
    *(float4*)(hout + (size_t)i * 4) = hn;
    if (outseq)
        *(float4*)(outseq + ((size_t)(img * 10) * NPIX + (pixg & 4095)) * 64 + f4) = hn;
}

// Weights -> fp16 B-fragment order with gate-interleaved columns:
// ctb (0..15): gate = ctb&3, choct = ctb>>2; col = gate*64 + half*32 + choct*8 + g
// k0 = tap*64 + kf*16 + 2*tg;  b0 = pack(W[k0][col],W[k0+1][col]), b1 = +8 rows.
__global__ void prep_w(const float* __restrict__ w0, const float* __restrict__ w1,
                       const float* __restrict__ w2) {
    int idx = blockIdx.x * 256 + threadIdx.x;      // uint2 index
    if (idx >= 3 * 36864) return;
    int which = idx / 36864;
    int rem   = idx - which * 36864;
    int half = rem / 18432;
    int r    = rem - half * 18432;
    int tap = r >> 11;
    int r2  = r & 2047;
    int kf  = r2 >> 9;
    int ctb = (r2 >> 5) & 15;
    int ln  = r2 & 31;
    int tg = ln & 3, gg = ln >> 2;
    int gate = ctb & 3, choct = ctb >> 2;
    const float* src = (which == 0) ? w0 : (which == 1) ? w1 : w2;
    int k0  = tap * 64 + kf * 16 + 2 * tg;
    int col = gate * 64 + half * 32 + choct * 8 + gg;
    __half2 b0 = __floats2half2_rn(src[(size_t)k0 * 256 + col],
                                   src[(size_t)(k0 + 1) * 256 + col]);
    __half2 b1 = __floats2half2_rn(src[(size_t)(k0 + 8) * 256 + col],
                                   src[(size_t)(k0 + 9) * 256 + col]);
    uint2 v;
    v.x = *(unsigned*)&b0;
    v.y = *(unsigned*)&b1;
    g_wtH[idx] = v;
}

// Layer-0 input conv (Cin=1), exact fp32, writes xg gate-minor:
// thread tid = source col (gate*64+f) -> stored at [pix][f*4 + gate].
__global__ void conv_l0(const float* __restrict__ x, const float* __restrict__ w,
                        const float* __restrict__ b, float* __restrict__ xg) {
    __shared__ float ps[18 * 18];
    __shared__ float ws[9 * C4];
    int img = blockIdx.y;
    int by0 = (blockIdx.x >> 2) * 16, bx0 = (blockIdx.x & 3) * 16;
    int tid = threadIdx.x;
    int perm = (tid & 63) * 4 + (tid >> 6);
    for (int i = tid; i < 324; i += 256) {
        int ly = i / 18, lx = i - ly * 18;
        int gy = by0 + ly - 1, gx = bx0 + lx - 1;
        float v = 0.0f;
        if (gy >= 0 && gy < HW && gx >= 0 && gx < HW)
            v = x[(size_t)img * NPIX + gy * HW + gx];
        ps[i] = v;
    }
    for (int i = tid; i < 9 * C4; i += 256) ws[i] = w[i];
    __syncthreads();
    float wr[9];
#pragma unroll
    for (int tp = 0; tp < 9; ++tp) wr[tp] = ws[tp * C4 + tid];
    float bv = b[tid];
    for (int p = 0; p < 256; ++p) {
        int py = p >> 4, px = p & 15;
        float a = bv;
#pragma unroll
        for (int tp = 0; tp < 9; ++tp) {
            int dy = tp / 3, dx = tp - 3 * dy;
            a += ps[(py + dy) * 18 + (px + dx)] * wr[tp];
        }
        xg[((size_t)img * NPIX + (by0 + py) * HW + (bx0 + px)) * C4 + perm] = a;
    }
}

// ---------------------------------------------------------------------------
// fp16 mma.sync conv block, N=128 half. MODE 1: LSTM step (sync-free fused
// epilogue); MODE 0: gates = conv + bias, written gate-minor (xg producer).
// 8 warps as 2(M) x 4(N); warp tile 32x32; 32 fp32 accumulators per thread.
// ---------------------------------------------------------------------------
template <int MODE>
__global__ void __launch_bounds__(256, 3)
mm_conv(const float* __restrict__ in, const uint2* __restrict__ wt,
        const float* __restrict__ xg_or_bias, float* __restrict__ gout,
        float* __restrict__ cbuf, float* __restrict__ hout,
        float* __restrict__ outseq, int tstep) {
    extern __shared__ float smf[];
    unsigned* Au = (unsigned*)smf;                 // A fp16x2 words
    unsigned sbase = smem_u32(smf);
    int tid = threadIdx.x;
    int wid = tid >> 5, lane = tid & 31;
    int g = lane >> 2, tg = lane & 3;
    int mw = wid >> 2, nw = wid & 3;
    int m_base = mw * 32;
    int img = blockIdx.y;
    int y0 = blockIdx.x >> 1;                  // image row handled by block
    int half = blockIdx.x & 1;                 // channel half (f 0-31 / 32-63)
    const float* inb = in + (size_t)img * (NPIX * FDIM);
    const uint2* wt2 = wt + half * 18432;
    int fglob = half * 32 + nw * 8 + 2 * tg;   // this thread's channel (even)
    // per-lane invariant part of ldmatrix addresses (words)
    int lanepart = (lane & 15) * 36 + ((lane >> 4) << 2);

    // ---- fill persistent A: [3][66 pos][32 ch-pairs], fp16x2, halo-padded --
    for (int i = tid; i < 6336; i += 256) {        // 3*66*32 words
        int dyi = i / 2112;
        int rem = i - dyi * 2112;
        int xx = rem >> 5;                         // 0..65  (pos = x+1)
        int cp = rem & 31;                         // channel pair
        int y = y0 + dyi - 1;
        int x = xx - 1;
        unsigned w = 0u;
        if ((unsigned)y < 64u && (unsigned)x < 64u) {
            float2 v = *(const float2*)(inb + (size_t)(((y << 6) + x) * 64 + cp * 2));
            __half2 h2 = __floats2half2_rn(v.x, v.y);
            w = *(unsigned*)&h2;
        }
        Au[dyi * 2376 + xx * 36 + cp] = w;
    }

    float acc[2][4][4];
#pragma unroll
    for (int mi = 0; mi < 2; ++mi)
#pragma unroll
        for (int ni = 0; ni < 4; ++ni)
#pragma unroll
            for (int r = 0; r < 4; ++r) acc[mi][ni][r] = 0.0f;

    auto issueB = [&](int s, int buf) {
        const uint4* wp = (const uint4*)(wt2 + (size_t)s * 2048);
        unsigned dbase = sbase + (unsigned)(BBASEB + buf * 16384);
#pragma unroll
        for (int i = 0; i < 4; ++i) {
            int idx = tid + i * 256;               // 0..1023 (16B chunks)
            unsigned daddr = dbase + (unsigned)idx * 16;
            asm volatile("cp.async.ca.shared.global [%0], [%1], 16;"
                         :: "r"(daddr), "l"(wp + idx));
        }
    };

    issueB(0, 0);
    asm volatile("cp.async.commit_group;");
    issueB(1, 1);
    asm volatile("cp.async.commit_group;");

    for (int s = 0; s < 9; ++s) {
        if (s < 8) asm volatile("cp.async.wait_group 1;");
        else       asm volatile("cp.async.wait_group 0;");
        __syncthreads();       // B(s) visible; A ready (s=0)

        int qy = s / 3;                            // dy+1
        int dx = s - 3 * qy - 1;
        const uint2* Bb = (const uint2*)((char*)smf + BBASEB + (s & 1) * 16384);
        int rowbase = qy * 2376 + (m_base + dx + 1) * 36 + lanepart;
        unsigned aaddr0 = sbase + (unsigned)rowbase * 4;
        unsigned aaddr1 = aaddr0 + 16 * 36 * 4;

#pragma unroll
        for (int kf = 0; kf < 4; ++kf) {
            unsigned a0[4], a1[4];
            ldm_x4(a0, aaddr0 + (unsigned)(kf * 8) * 4);
            ldm_x4(a1, aaddr1 + (unsigned)(kf * 8) * 4);
            const uint2* bp = Bb + (kf << 9) + (nw << 7) + lane;
#pragma unroll
            for (int ni = 0; ni < 4; ++ni) {
                uint2 bb = bp[ni * 32];
                MMA_F16(acc[0][ni], a0, bb.x, bb.y);
                MMA_F16(acc[1][ni], a1, bb.x, bb.y);
            }
        }
        __syncthreads();       // all warps done with BF[s&1] before refill
        if (s + 2 < 9) {
            issueB(s + 2, s & 1);
            asm volatile("cp.async.commit_group;");
        }
    }

    // ---- epilogue (no smem, no barriers: thread owns i,f,g,o) ------------
    if (MODE == 0) {
        // gates -> gout gate-minor [pix][f][4], + bias
        float bi[2][4];
#pragma unroll
        for (int j = 0; j < 2; ++j)
#pragma unroll
            for (int k = 0; k < 4; ++k)
                bi[j][k] = xg_or_bias[k * 64 + fglob + j];
#pragma unroll
        for (int mi = 0; mi < 2; ++mi)
#pragma unroll
            for (int rh = 0; rh < 2; ++rh) {
                int pix = y0 * 64 + m_base + mi * 16 + rh * 8 + g;
                float* ob = gout + ((size_t)img * NPIX + pix) * 256 + (size_t)fglob * 4;
                int cb = rh * 2;
#pragma unroll
                for (int j = 0; j < 2; ++j) {
                    float4 v = make_float4(acc[mi][0][cb + j] + bi[j][0],
                                           acc[mi][1][cb + j] + bi[j][1],
                                           acc[mi][2][cb + j] + bi[j][2],
                                           acc[mi][3][cb + j] + bi[j][3]);
                    *(float4*)(ob + j * 4) = v;
                }
            }
    } else {
#pragma unroll
        for (int mi = 0; mi < 2; ++mi)
#pragma unroll
            for (int rh = 0; rh < 2; ++rh) {
                int pix = y0 * 64 + m_base + mi * 16 + rh * 8 + g;
                const float4* xq = (const float4*)(xg_or_bias +
                    ((size_t)(img * 10 + tstep) * NPIX + pix) * 256 + (size_t)fglob * 4);
                float4 q0 = xq[0], q1 = xq[1];          // (i,f,g,o) for ch, ch+1
                size_t hoff = ((size_t)img * NPIX + pix) * 64 + fglob;
                float2 co = *(const float2*)(cbuf + hoff);
                int cb = rh * 2;
                float cn0 = hsig(acc[mi][1][cb] + q0.y) * co.x
                          + hsig(acc[mi][0][cb] + q0.x) * tanhf(acc[mi][2][cb] + q0.z);
                float cn1 = hsig(acc[mi][1][cb + 1] + q1.y) * co.y
                          + hsig(acc[mi][0][cb + 1] + q1.x) * tanhf(acc[mi][2][cb + 1] + q1.z);
                float hn0 = hsig(acc[mi][3][cb] + q0.w) * tanhf(cn0);
                float hn1 = hsig(acc[mi][3][cb + 1] + q1.w) * tanhf(cn1);
                *(float2*)(cbuf + hoff) = make_float2(cn0, cn1);
                *(float2*)(hout + hoff) = make_float2(hn0, hn1);
                if (outseq)
                    *(float2*)(outseq + ((size_t)(img * 10 + tstep) * NPIX + pix) * 64
                               + fglob) = make_float2(hn0, hn1);
            }
    }
}

// ---------------------------------------------------------------------------
extern "C" void kernel_launch(void* const* d_in, const int* in_sizes, int n_in,
                              void* d_out, int out_size) {
    const float* x   = (const float*)d_in[0];
    const float* Wx0 = (const float*)d_in[1];
    const float* Wh0 = (const float*)d_in[2];
    const float* b0  = (const float*)d_in[3];
    const float* Wx1 = (const float*)d_in[4];
    const float* Wh1 = (const float*)d_in[5];
    const float* b1  = (const float*)d_in[6];
    float* out = (float*)d_out;

    float *xg0, *xg1, *out0, *hbase, *cb;
    uint2* wt;
    cudaGetSymbolAddress((void**)&xg0,   g_xg0);
    cudaGetSymbolAddress((void**)&xg1,   g_xg1);
    cudaGetSymbolAddress((void**)&out0,  g_out0);
    cudaGetSymbolAddress((void**)&hbase, g_h);
    cudaGetSymbolAddress((void**)&cb,    g_c);
    cudaGetSymbolAddress((void**)&wt,    g_wtH);
    float* hb[2] = { hbase, hbase + SEG };

    cudaFuncSetAttribute(mm_conv<1>, cudaFuncAttributeMaxDynamicSharedMemorySize, SMEM_BYTES);
    cudaFuncSetAttribute(mm_conv<0>, cudaFuncAttributeMaxDynamicSharedMemorySize, SMEM_BYTES);

    // fp16 fragment-order gate-interleaved weights: [0]=Wh0, [1]=Wx1, [2]=Wh1
    prep_w<<<432, 256>>>(Wh0, Wx1, Wh1);

    // Layer-0 input conv (exact fp32, gate-minor xg)
    conv_l0<<<dim3(16, 80), 256>>>(x, Wx0, b0, xg0);

    // Layer 0: t=0 exact init, then t=1..9 conv steps
    lstm_init<<<2048, 256>>>(xg0, cb, hb[1], out0);
    for (int t = 1; t < 10; ++t)
        mm_conv<1><<<dim3(128, 8), 256, SMEM_BYTES>>>(
            hb[t & 1], wt, xg0, nullptr, cb, hb[(t + 1) & 1], out0, t);
    gather_out<<<2048, 1024>>>(out, 0);

    // Layer-1 batched input conv over 80 images (produces gate-minor xg1)
    mm_conv<0><<<dim3(128, 80), 256, SMEM_BYTES>>>(
        out0, wt + 36864, b1, xg1, nullptr, nullptr, nullptr, 0);

    // Layer 1: t=0 exact init, then t=1..9 conv steps
    lstm_init<<<2048, 256>>>(xg1, cb, hb[1], nullptr);
    for (int t = 1; t < 10; ++t)
        mm_conv<1><<<dim3(128, 8), 256, SMEM_BYTES>>>(
            hb[t & 1], wt + 2 * 36864, xg1, nullptr, cb, hb[(t + 1) & 1], nullptr, t);
    gather_out<<<2048, 1024>>>(out, 1);

    (void)in_sizes; (void)n_in; (void)out_size;
}

// round 12
// speedup vs baseline: 2.2778x; 1.1892x over previous
#include <cuda_runtime.h>
#include <cuda_fp16.h>
#include <math.h>
#include <stdint.h>

// ---------------------------------------------------------------------------
// B=8, T=10, H=W=64, Cin=1, F=64, 4F=256, k=3x3 SAME.
// Output: [2][2][8][64][64][64] fp32.
// fp16 mma.sync (m16n8k16, fp32 accum) implicit-GEMM conv.
// Per block: M=64 positions (one image row) x N=128 (one channel-half, gates
// interleaved), K=576 as 9 taps. Warp tile 32x32 -> 32 accums -> 3 blocks/SM.
// A (3 h-rows) persistent in smem (ldmatrix.x4); B fragments loaded DIRECTLY
// from gmem (LDG.64, L2-broadcast across blocks) -> mainloop is barrier-free.
// t=0 steps replaced by exact elementwise init; t=9 writes h,c into d_out.
// ---------------------------------------------------------------------------

#define HW    64
#define FDIM  64
#define C4    256
#define NPIX  4096
#define SEG   2097152            // 8*4096*64

__device__ float g_xg0[10 * 8 * NPIX * C4];   // gate-minor: [timg][pix][f][4]
__device__ float g_xg1[10 * 8 * NPIX * C4];
__device__ float g_out0[10 * 8 * NPIX * FDIM];
__device__ float g_h[2][SEG];
__device__ float g_c[SEG];
// fp16 fragment-ordered weights:
// uint2[which(3)][half(2)][tap(9)][kf(4)][ctb(16)][lane(32)]
__device__ uint2 g_wtH[3 * 2 * 9 * 4 * 16 * 32];

__device__ __forceinline__ float hsig(float x) {
    return fminf(fmaxf(0.2f * x + 0.5f, 0.0f), 1.0f);
}
__device__ __forceinline__ unsigned smem_u32(const void* p) {
    unsigned r;
    asm("{ .reg .u64 t; cvta.to.shared.u64 t, %1; cvt.u32.u64 %0, t; }"
        : "=r"(r) : "l"(p));
    return r;
}
__device__ __forceinline__ void ldm_x4(unsigned* a, unsigned addr) {
    asm volatile("ldmatrix.sync.aligned.m8n8.x4.shared.b16 {%0,%1,%2,%3}, [%4];"
        : "=r"(a[0]), "=r"(a[1]), "=r"(a[2]), "=r"(a[3]) : "r"(addr));
}

#define MMA_F16(c, a, bx, by)                                                  \
    asm volatile("mma.sync.aligned.m16n8k16.row.col.f32.f16.f16.f32 "          \
        "{%0,%1,%2,%3}, {%4,%5,%6,%7}, {%8,%9}, {%0,%1,%2,%3};"                \
        : "+f"(c[0]), "+f"(c[1]), "+f"(c[2]), "+f"(c[3])                       \
        : "r"(a[0]), "r"(a[1]), "r"(a[2]), "r"(a[3]), "r"(bx), "r"(by))

// smem: A fp16x2 words [3][66][36] = 7128 u32 (pos stride 36 words). 28512B.
#define SMEM_BYTES 28672

// ---------------------------------------------------------------------------
// t=0 LSTM step, exact (h_prev=0 -> gates = xg). xg is gate-minor [pix][f][4].
__global__ void lstm_init(const float* __restrict__ xg, float* __restrict__ cbuf,
                          float* __restrict__ hout, float* __restrict__ outseq) {
    int i = blockIdx.x * blockDim.x + threadIdx.x;     // float4 index in [pix][64]
    if (i >= SEG / 4) return;
    int f4 = (i & 15) << 2;                             // channel base
    int pixg = i >> 4;                                  // img*4096 + pix
    int img = pixg >> 12;
    const float4* xp = (const float4*)(xg +
        ((size_t)(img * 10) * NPIX + (pixg & 4095)) * 256 + (size_t)f4 * 4);
    float4 cn, hn;
    {
        float4 q0 = xp[0], q1 = xp[1], q2 = xp[2], q3 = xp[3];  // (i,f,g,o) x 4 ch
        cn.x = hsig(q0.x) * tanhf(q0.z);
        cn.y = hsig(q1.x) * tanhf(q1.z);
        cn.z = hsig(q2.x) * tanhf(q2.z);
        cn.w = hsig(q3.x) * tanhf(q3.z);
        hn.x = hsig(q0.w) * tanhf(cn.x);
        hn.y = hsig(q1.w) * tanhf(cn.y);
        hn.z = hsig(q2.w) * tanhf(cn.z);
        hn.w = hsig(q3.w) * tanhf(cn.w);
    }
    *(float4*)(cbuf + (size_t)i * 4) = cn;
    *(float4*)(hout + (size_t)i * 4) = hn;
    if (outseq)
        *(float4*)(outseq + ((size_t)(img * 10) * NPIX + (pixg & 4095)) * 64 + f4) = hn;
}

// Weights -> fp16 B-fragment order with gate-interleaved columns:
// ctb (0..15): gate = ctb&3, choct = ctb>>2; col = gate*64 + half*32 + choct*8 + g
// k0 = tap*64 + kf*16 + 2*tg;  b0 = pack(W[k0][col],W[k0+1][col]), b1 = +8 rows.
__global__ void prep_w(const float* __restrict__ w0, const float* __restrict__ w1,
                       const float* __restrict__ w2) {
    int idx = blockIdx.x * 256 + threadIdx.x;      // uint2 index
    if (idx >= 3 * 36864) return;
    int which = idx / 36864;
    int rem   = idx - which * 36864;
    int half = rem / 18432;
    int r    = rem - half * 18432;
    int tap = r >> 11;
    int r2  = r & 2047;
    int kf  = r2 >> 9;
    int ctb = (r2 >> 5) & 15;
    int ln  = r2 & 31;
    int tg = ln & 3, gg = ln >> 2;
    int gate = ctb & 3, choct = ctb >> 2;
    const float* src = (which == 0) ? w0 : (which == 1) ? w1 : w2;
    int k0  = tap * 64 + kf * 16 + 2 * tg;
    int col = gate * 64 + half * 32 + choct * 8 + gg;
    __half2 b0 = __floats2half2_rn(src[(size_t)k0 * 256 + col],
                                   src[(size_t)(k0 + 1) * 256 + col]);
    __half2 b1 = __floats2half2_rn(src[(size_t)(k0 + 8) * 256 + col],
                                   src[(size_t)(k0 + 9) * 256 + col]);
    uint2 v;
    v.x = *(unsigned*)&b0;
    v.y = *(unsigned*)&b1;
    g_wtH[idx] = v;
}

// Layer-0 input conv (Cin=1), exact fp32, writes xg gate-minor:
// thread tid = source col (gate*64+f) -> stored at [pix][f*4 + gate].
__global__ void conv_l0(const float* __restrict__ x, const float* __restrict__ w,
                        const float* __restrict__ b, float* __restrict__ xg) {
    __shared__ float ps[18 * 18];
    __shared__ float ws[9 * C4];
    int img = blockIdx.y;
    int by0 = (blockIdx.x >> 2) * 16, bx0 = (blockIdx.x & 3) * 16;
    int tid = threadIdx.x;
    int perm = (tid & 63) * 4 + (tid >> 6);
    for (int i = tid; i < 324; i += 256) {
        int ly = i / 18, lx = i - ly * 18;
        int gy = by0 + ly - 1, gx = bx0 + lx - 1;
        float v = 0.0f;
        if (gy >= 0 && gy < HW && gx >= 0 && gx < HW)
            v = x[(size_t)img * NPIX + gy * HW + gx];
        ps[i] = v;
    }
    for (int i = tid; i < 9 * C4; i += 256) ws[i] = w[i];
    __syncthreads();
    float wr[9];
#pragma unroll
    for (int tp = 0; tp < 9; ++tp) wr[tp] = ws[tp * C4 + tid];
    float bv = b[tid];
    for (int p = 0; p < 256; ++p) {
        int py = p >> 4, px = p & 15;
        float a = bv;
#pragma unroll
        for (int tp = 0; tp < 9; ++tp) {
            int dy = tp / 3, dx = tp - 3 * dy;
            a += ps[(py + dy) * 18 + (px + dx)] * wr[tp];
        }
        xg[((size_t)img * NPIX + (by0 + py) * HW + (bx0 + px)) * C4 + perm] = a;
    }
}

// ---------------------------------------------------------------------------
// fp16 mma.sync conv block, N=128 half. MODE 1: LSTM step (sync-free fused
// epilogue; optional finalout writes h,c into d_out at t=9); MODE 0: gates =
// conv + bias, written gate-minor (xg producer).
// 8 warps as 2(M) x 4(N); warp tile 32x32; 32 fp32 accumulators per thread.
// B fragments via direct LDG (no smem, no barriers in mainloop).
// ---------------------------------------------------------------------------
template <int MODE>
__global__ void __launch_bounds__(256, 3)
mm_conv(const float* __restrict__ in, const uint2* __restrict__ wt,
        const float* __restrict__ xg_or_bias, float* __restrict__ gout,
        float* __restrict__ cbuf, float* __restrict__ hout,
        float* __restrict__ outseq, float* __restrict__ finalout, int tstep) {
    extern __shared__ float smf[];
    unsigned* Au = (unsigned*)smf;                 // A fp16x2 words
    unsigned sbase = smem_u32(smf);
    int tid = threadIdx.x;
    int wid = tid >> 5, lane = tid & 31;
    int g = lane >> 2, tg = lane & 3;
    int mw = wid >> 2, nw = wid & 3;
    int m_base = mw * 32;
    int img = blockIdx.y;
    int y0 = blockIdx.x >> 1;                  // image row handled by block
    int half = blockIdx.x & 1;                 // channel half (f 0-31 / 32-63)
    const float* inb = in + (size_t)img * (NPIX * FDIM);
    const uint2* wt2 = wt + half * 18432;
    int fglob = half * 32 + nw * 8 + 2 * tg;   // this thread's channel (even)
    // per-lane invariant part of ldmatrix addresses (words)
    int lanepart = (lane & 15) * 36 + ((lane >> 4) << 2);

    // ---- fill persistent A: [3][66 pos][32 ch-pairs], fp16x2, halo-padded --
    for (int i = tid; i < 6336; i += 256) {        // 3*66*32 words
        int dyi = i / 2112;
        int rem = i - dyi * 2112;
        int xx = rem >> 5;                         // 0..65  (pos = x+1)
        int cp = rem & 31;                         // channel pair
        int y = y0 + dyi - 1;
        int x = xx - 1;
        unsigned w = 0u;
        if ((unsigned)y < 64u && (unsigned)x < 64u) {
            float2 v = *(const float2*)(inb + (size_t)(((y << 6) + x) * 64 + cp * 2));
            __half2 h2 = __floats2half2_rn(v.x, v.y);
            w = *(unsigned*)&h2;
        }
        Au[dyi * 2376 + xx * 36 + cp] = w;
    }

    float acc[2][4][4];
#pragma unroll
    for (int mi = 0; mi < 2; ++mi)
#pragma unroll
        for (int ni = 0; ni < 4; ++ni)
#pragma unroll
            for (int r = 0; r < 4; ++r) acc[mi][ni][r] = 0.0f;

    __syncthreads();                               // A ready; only barrier

    const uint2* bwarp = wt2 + (nw << 7) + lane;   // + s*2048 + kf*512 + ni*32

#pragma unroll
    for (int s = 0; s < 9; ++s) {
        const int qy = s / 3;                      // dy+1 (compile-time)
        const int dx = s - 3 * qy - 1;
        int rowbase = qy * 2376 + (m_base + dx + 1) * 36 + lanepart;
        unsigned aaddr0 = sbase + (unsigned)rowbase * 4;
        unsigned aaddr1 = aaddr0 + 16 * 36 * 4;
        const uint2* bs = bwarp + s * 2048;

#pragma unroll
        for (int kf = 0; kf < 4; ++kf) {
            uint2 bb0 = bs[(kf << 9)];
            uint2 bb1 = bs[(kf << 9) + 32];
            uint2 bb2 = bs[(kf << 9) + 64];
            uint2 bb3 = bs[(kf << 9) + 96];
            unsigned a0[4], a1[4];
            ldm_x4(a0, aaddr0 + (unsigned)(kf * 32));
            ldm_x4(a1, aaddr1 + (unsigned)(kf * 32));
            MMA_F16(acc[0][0], a0, bb0.x, bb0.y);
            MMA_F16(acc[1][0], a1, bb0.x, bb0.y);
            MMA_F16(acc[0][1], a0, bb1.x, bb1.y);
            MMA_F16(acc[1][1], a1, bb1.x, bb1.y);
            MMA_F16(acc[0][2], a0, bb2.x, bb2.y);
            MMA_F16(acc[1][2], a1, bb2.x, bb2.y);
            MMA_F16(acc[0][3], a0, bb3.x, bb3.y);
            MMA_F16(acc[1][3], a1, bb3.x, bb3.y);
        }
    }

    // ---- epilogue (no smem, no barriers: thread owns i,f,g,o) ------------
    if (MODE == 0) {
        // gates -> gout gate-minor [pix][f][4], + bias
        float bi[2][4];
#pragma unroll
        for (int j = 0; j < 2; ++j)
#pragma unroll
            for (int k = 0; k < 4; ++k)
                bi[j][k] = xg_or_bias[k * 64 + fglob + j];
#pragma unroll
        for (int mi = 0; mi < 2; ++mi)
#pragma unroll
            for (int rh = 0; rh < 2; ++rh) {
                int pix = y0 * 64 + m_base + mi * 16 + rh * 8 + g;
                float* ob = gout + ((size_t)img * NPIX + pix) * 256 + (size_t)fglob * 4;
                int cb = rh * 2;
#pragma unroll
                for (int j = 0; j < 2; ++j) {
                    float4 v = make_float4(acc[mi][0][cb + j] + bi[j][0],
                                           acc[mi][1][cb + j] + bi[j][1],
                                           acc[mi][2][cb + j] + bi[j][2],
                                           acc[mi][3][cb + j] + bi[j][3]);
                    *(float4*)(ob + j * 4) = v;
                }
            }
    } else {
#pragma unroll
        for (int mi = 0; mi < 2; ++mi)
#pragma unroll
            for (int rh = 0; rh < 2; ++rh) {
                int pix = y0 * 64 + m_base + mi * 16 + rh * 8 + g;
                const float4* xq = (const float4*)(xg_or_bias +
                    ((size_t)(img * 10 + tstep) * NPIX + pix) * 256 + (size_t)fglob * 4);
                float4 q0 = xq[0], q1 = xq[1];          // (i,f,g,o) for ch, ch+1
                size_t hoff = ((size_t)img * NPIX + pix) * 64 + fglob;
                float2 co = *(const float2*)(cbuf + hoff);
                int cb = rh * 2;
                float cn0 = hsig(acc[mi][1][cb] + q0.y) * co.x
                          + hsig(acc[mi][0][cb] + q0.x) * tanhf(acc[mi][2][cb] + q0.z);
                float cn1 = hsig(acc[mi][1][cb + 1] + q1.y) * co.y
                          + hsig(acc[mi][0][cb + 1] + q1.x) * tanhf(acc[mi][2][cb + 1] + q1.z);
                float hn0 = hsig(acc[mi][3][cb] + q0.w) * tanhf(cn0);
                float hn1 = hsig(acc[mi][3][cb + 1] + q1.w) * tanhf(cn1);
                if (finalout) {                      // t=9: write h,c to d_out
                    *(float2*)(finalout + hoff)       = make_float2(hn0, hn1);
                    *(float2*)(finalout + SEG + hoff) = make_float2(cn0, cn1);
                } else {
                    *(float2*)(cbuf + hoff) = make_float2(cn0, cn1);
                    *(float2*)(hout + hoff) = make_float2(hn0, hn1);
                }
                if (outseq)
                    *(float2*)(outseq + ((size_t)(img * 10 + tstep) * NPIX + pix) * 64
                               + fglob) = make_float2(hn0, hn1);
            }
    }
}

// ---------------------------------------------------------------------------
extern "C" void kernel_launch(void* const* d_in, const int* in_sizes, int n_in,
                              void* d_out, int out_size) {
    const float* x   = (const float*)d_in[0];
    const float* Wx0 = (const float*)d_in[1];
    const float* Wh0 = (const float*)d_in[2];
    const float* b0  = (const float*)d_in[3];
    const float* Wx1 = (const float*)d_in[4];
    const float* Wh1 = (const float*)d_in[5];
    const float* b1  = (const float*)d_in[6];
    float* out = (float*)d_out;

    float *xg0, *xg1, *out0, *hbase, *cb;
    uint2* wt;
    cudaGetSymbolAddress((void**)&xg0,   g_xg0);
    cudaGetSymbolAddress((void**)&xg1,   g_xg1);
    cudaGetSymbolAddress((void**)&out0,  g_out0);
    cudaGetSymbolAddress((void**)&hbase, g_h);
    cudaGetSymbolAddress((void**)&cb,    g_c);
    cudaGetSymbolAddress((void**)&wt,    g_wtH);
    float* hb[2] = { hbase, hbase + SEG };

    cudaFuncSetAttribute(mm_conv<1>, cudaFuncAttributeMaxDynamicSharedMemorySize, SMEM_BYTES);
    cudaFuncSetAttribute(mm_conv<0>, cudaFuncAttributeMaxDynamicSharedMemorySize, SMEM_BYTES);

    // fp16 fragment-order gate-interleaved weights: [0]=Wh0, [1]=Wx1, [2]=Wh1
    prep_w<<<432, 256>>>(Wh0, Wx1, Wh1);

    // Layer-0 input conv (exact fp32, gate-minor xg)
    conv_l0<<<dim3(16, 80), 256>>>(x, Wx0, b0, xg0);

    // Layer 0: t=0 exact init, t=1..8 steps, t=9 step writes d_out layer 0
    lstm_init<<<2048, 256>>>(xg0, cb, hb[1], out0);
    for (int t = 1; t < 9; ++t)
        mm_conv<1><<<dim3(128, 8), 256, SMEM_BYTES>>>(
            hb[t & 1], wt, xg0, nullptr, cb, hb[(t + 1) & 1], out0, nullptr, t);
    mm_conv<1><<<dim3(128, 8), 256, SMEM_BYTES>>>(
        hb[1], wt, xg0, nullptr, cb, nullptr, out0, out, 9);

    // Layer-1 batched input conv over 80 images (produces gate-minor xg1)
    mm_conv<0><<<dim3(128, 80), 256, SMEM_BYTES>>>(
        out0, wt + 36864, b1, xg1, nullptr, nullptr, nullptr, nullptr, 0);

    // Layer 1: t=0 exact init, t=1..8 steps, t=9 step writes d_out layer 1
    lstm_init<<<2048, 256>>>(xg1, cb, hb[1], nullptr);
    for (int t = 1; t < 9; ++t)
        mm_conv<1><<<dim3(128, 8), 256, SMEM_BYTES>>>(
            hb[t & 1], wt + 2 * 36864, xg1, nullptr, cb, hb[(t + 1) & 1], nullptr,
            nullptr, t);
    mm_conv<1><<<dim3(128, 8), 256, SMEM_BYTES>>>(
        hb[1], wt + 2 * 36864, xg1, nullptr, cb, nullptr, nullptr, out + 2 * SEG, 9);

    (void)in_sizes; (void)n_in; (void)out_size;
}

// round 13
// speedup vs baseline: 2.5237x; 1.1079x over previous
#include <cuda_runtime.h>
#include <cuda_fp16.h>
#include <math.h>
#include <stdint.h>

// ---------------------------------------------------------------------------
// B=8, T=10, H=W=64, Cin=1, F=64, 4F=256, k=3x3 SAME.
// Output: [2][2][8][64][64][64] fp32.
// fp16 mma.sync (m16n8k16, fp32 accum) implicit-GEMM conv.
// Per block: M=64 positions (one image row) x N=128 (one channel-half, gates
// interleaved), K=576 as 9 taps. Warp tile 32x32 -> 32 accums -> 3 blocks/SM.
// h and out0 are stored as fp16 (bit-identical to the old fp32->fp16 convert
// path), so the A-fill is a pure cp.async copy with zero-fill halo. B frags
// loaded directly from gmem (L2-broadcast). Mainloop barrier-free.
// t=0 steps are an exact elementwise init; t=9 writes h,c into d_out.
// ---------------------------------------------------------------------------

#define HW    64
#define FDIM  64
#define C4    256
#define NPIX  4096
#define SEG   2097152            // 8*4096*64

__device__ float  g_xg0[10 * 8 * NPIX * C4];   // gate-minor: [timg][pix][f][4]
__device__ float  g_xg1[10 * 8 * NPIX * C4];
__device__ __half g_out0H[10 * 8 * NPIX * FDIM];
__device__ __half g_hH[2][SEG];
__device__ float  g_c[SEG];
// fp16 fragment-ordered weights:
// uint2[which(3)][half(2)][tap(9)][kf(4)][ctb(16)][lane(32)]
__device__ uint2 g_wtH[3 * 2 * 9 * 4 * 16 * 32];

__device__ __forceinline__ float hsig(float x) {
    return fminf(fmaxf(0.2f * x + 0.5f, 0.0f), 1.0f);
}
__device__ __forceinline__ unsigned smem_u32(const void* p) {
    unsigned r;
    asm("{ .reg .u64 t; cvta.to.shared.u64 t, %1; cvt.u32.u64 %0, t; }"
        : "=r"(r) : "l"(p));
    return r;
}
__device__ __forceinline__ void ldm_x4(unsigned* a, unsigned addr) {
    asm volatile("ldmatrix.sync.aligned.m8n8.x4.shared.b16 {%0,%1,%2,%3}, [%4];"
        : "=r"(a[0]), "=r"(a[1]), "=r"(a[2]), "=r"(a[3]) : "r"(addr));
}

#define MMA_F16(c, a, bx, by)                                                  \
    asm volatile("mma.sync.aligned.m16n8k16.row.col.f32.f16.f16.f32 "          \
        "{%0,%1,%2,%3}, {%4,%5,%6,%7}, {%8,%9}, {%0,%1,%2,%3};"                \
        : "+f"(c[0]), "+f"(c[1]), "+f"(c[2]), "+f"(c[3])                       \
        : "r"(a[0]), "r"(a[1]), "r"(a[2]), "r"(a[3]), "r"(bx), "r"(by))

// smem: A fp16x2 words [3][66][36] = 7128 u32 (pos stride 36 words). 28512B.
#define SMEM_BYTES 28672

// ---------------------------------------------------------------------------
// t=0 LSTM step, exact (h_prev=0 -> gates = xg). xg is gate-minor [pix][f][4].
__global__ void lstm_init(const float* __restrict__ xg, float* __restrict__ cbuf,
                          __half* __restrict__ hout, __half* __restrict__ outseq) {
    int i = blockIdx.x * blockDim.x + threadIdx.x;     // float4 index in [pix][64]
    if (i >= SEG / 4) return;
    int f4 = (i & 15) << 2;                             // channel base
    int pixg = i >> 4;                                  // img*4096 + pix
    int img = pixg >> 12;
    const float4* xp = (const float4*)(xg +
        ((size_t)(img * 10) * NPIX + (pixg & 4095)) * 256 + (size_t)f4 * 4);
    float4 cn, hn;
    {
        float4 q0 = xp[0], q1 = xp[1], q2 = xp[2], q3 = xp[3];  // (i,f,g,o) x 4 ch
        cn.x = hsig(q0.x) * tanhf(q0.z);
        cn.y = hsig(q1.x) * tanhf(q1.z);
        cn.z = hsig(q2.x) * tanhf(q2.z);
        cn.w = hsig(q3.x) * tanhf(q3.z);
        hn.x = hsig(q0.w) * tanhf(cn.x);
        hn.y = hsig(q1.w) * tanhf(cn.y);
        hn.z = hsig(q2.w) * tanhf(cn.z);
        hn.w = hsig(q3.w) * tanhf(cn.w);
    }
    *(float4*)(cbuf + (size_t)i * 4) = cn;
    __half2 h01 = __floats2half2_rn(hn.x, hn.y);
    __half2 h23 = __floats2half2_rn(hn.z, hn.w);
    *(__half2*)(hout + (size_t)i * 4)     = h01;
    *(__half2*)(hout + (size_t)i * 4 + 2) = h23;
    if (outseq) {
        __half* op = outseq + ((size_t)(img * 10) * NPIX + (pixg & 4095)) * 64 + f4;
        *(__half2*)(op)     = h01;
        *(__half2*)(op + 2) = h23;
    }
}

// Weights -> fp16 B-fragment order with gate-interleaved columns:
// ctb (0..15): gate = ctb&3, choct = ctb>>2; col = gate*64 + half*32 + choct*8 + g
// k0 = tap*64 + kf*16 + 2*tg;  b0 = pack(W[k0][col],W[k0+1][col]), b1 = +8 rows.
__global__ void prep_w(const float* __restrict__ w0, const float* __restrict__ w1,
                       const float* __restrict__ w2) {
    int idx = blockIdx.x * 256 + threadIdx.x;      // uint2 index
    if (idx >= 3 * 36864) return;
    int which = idx / 36864;
    int rem   = idx - which * 36864;
    int half = rem / 18432;
    int r    = rem - half * 18432;
    int tap = r >> 11;
    int r2  = r & 2047;
    int kf  = r2 >> 9;
    int ctb = (r2 >> 5) & 15;
    int ln  = r2 & 31;
    int tg = ln & 3, gg = ln >> 2;
    int gate = ctb & 3, choct = ctb >> 2;
    const float* src = (which == 0) ? w0 : (which == 1) ? w1 : w2;
    int k0  = tap * 64 + kf * 16 + 2 * tg;
    int col = gate * 64 + half * 32 + choct * 8 + gg;
    __half2 b0 = __floats2half2_rn(src[(size_t)k0 * 256 + col],
                                   src[(size_t)(k0 + 1) * 256 + col]);
    __half2 b1 = __floats2half2_rn(src[(size_t)(k0 + 8) * 256 + col],
                                   src[(size_t)(k0 + 9) * 256 + col]);
    uint2 v;
    v.x = *(unsigned*)&b0;
    v.y = *(unsigned*)&b1;
    g_wtH[idx] = v;
}

// Layer-0 input conv (Cin=1), exact fp32, writes xg gate-minor:
// thread tid = source col (gate*64+f) -> stored at [pix][f*4 + gate].
__global__ void conv_l0(const float* __restrict__ x, const float* __restrict__ w,
                        const float* __restrict__ b, float* __restrict__ xg) {
    __shared__ float ps[18 * 18];
    __shared__ float ws[9 * C4];
    int img = blockIdx.y;
    int by0 = (blockIdx.x >> 2) * 16, bx0 = (blockIdx.x & 3) * 16;
    int tid = threadIdx.x;
    int perm = (tid & 63) * 4 + (tid >> 6);
    for (int i = tid; i < 324; i += 256) {
        int ly = i / 18, lx = i - ly * 18;
        int gy = by0 + ly - 1, gx = bx0 + lx - 1;
        float v = 0.0f;
        if (gy >= 0 && gy < HW && gx >= 0 && gx < HW)
            v = x[(size_t)img * NPIX + gy * HW + gx];
        ps[i] = v;
    }
    for (int i = tid; i < 9 * C4; i += 256) ws[i] = w[i];
    __syncthreads();
    float wr[9];
#pragma unroll
    for (int tp = 0; tp < 9; ++tp) wr[tp] = ws[tp * C4 + tid];
    float bv = b[tid];
    for (int p = 0; p < 256; ++p) {
        int py = p >> 4, px = p & 15;
        float a = bv;
#pragma unroll
        for (int tp = 0; tp < 9; ++tp) {
            int dy = tp / 3, dx = tp - 3 * dy;
            a += ps[(py + dy) * 18 + (px + dx)] * wr[tp];
        }
        xg[((size_t)img * NPIX + (by0 + py) * HW + (bx0 + px)) * C4 + perm] = a;
    }
}

// ---------------------------------------------------------------------------
// fp16 mma.sync conv block, N=128 half. MODE 1: LSTM step (sync-free fused
// epilogue; optional finalout writes fp32 h,c into d_out at t=9); MODE 0:
// gates = conv + bias, written gate-minor fp32 (xg producer).
// 8 warps as 2(M) x 4(N); warp tile 32x32; 32 fp32 accumulators per thread.
// A (fp16 h rows) filled by cp.async with zero-fill halo; B frags direct LDG.
// ---------------------------------------------------------------------------
template <int MODE>
__global__ void __launch_bounds__(256, 3)
mm_conv(const __half* __restrict__ in, const uint2* __restrict__ wt,
        const float* __restrict__ xg_or_bias, float* __restrict__ gout,
        float* __restrict__ cbuf, __half* __restrict__ hout,
        __half* __restrict__ outseq, float* __restrict__ finalout, int tstep) {
    extern __shared__ float smf[];
    unsigned sbase = smem_u32(smf);
    int tid = threadIdx.x;
    int wid = tid >> 5, lane = tid & 31;
    int g = lane >> 2, tg = lane & 3;
    int mw = wid >> 2, nw = wid & 3;
    int m_base = mw * 32;
    int img = blockIdx.y;
    int y0 = blockIdx.x >> 1;                  // image row handled by block
    int half = blockIdx.x & 1;                 // channel half (f 0-31 / 32-63)
    const __half* inb = in + (size_t)img * (NPIX * FDIM);
    const uint2* wt2 = wt + half * 18432;
    int fglob = half * 32 + nw * 8 + 2 * tg;   // this thread's channel (even)
    // per-lane invariant part of ldmatrix addresses (words)
    int lanepart = (lane & 15) * 36 + ((lane >> 4) << 2);

    // ---- fill persistent A via cp.async: [3][66 pos][32 words], halo=0 ----
    // 1584 16B chunks: (dyi, xx, w4) with w4 in {0,4,...,28} words.
    for (int i = tid; i < 1584; i += 256) {
        int dyi = i / 528;
        int rem = i - dyi * 528;
        int xx = rem >> 3;                         // 0..65 (pos)
        int w4 = (rem & 7) << 2;                   // word offset in row
        int y = y0 + dyi - 1;
        int x = xx - 1;
        bool ok = ((unsigned)y < 64u) && ((unsigned)x < 64u);
        const __half* src = ok ? inb + (size_t)(((y << 6) + x) * 64 + (w4 << 1))
                               : inb;
        unsigned daddr = sbase + (unsigned)(dyi * 2376 + xx * 36 + w4) * 4;
        int sz = ok ? 16 : 0;
        asm volatile("cp.async.ca.shared.global [%0], [%1], 16, %2;"
                     :: "r"(daddr), "l"(src), "r"(sz));
    }
    asm volatile("cp.async.commit_group;");

    float acc[2][4][4];
#pragma unroll
    for (int mi = 0; mi < 2; ++mi)
#pragma unroll
        for (int ni = 0; ni < 4; ++ni)
#pragma unroll
            for (int r = 0; r < 4; ++r) acc[mi][ni][r] = 0.0f;

    asm volatile("cp.async.wait_group 0;");
    __syncthreads();                               // A ready; only barrier

    const uint2* bwarp = wt2 + (nw << 7) + lane;   // + s*2048 + kf*512 + ni*32

#pragma unroll
    for (int s = 0; s < 9; ++s) {
        const int qy = s / 3;                      // dy+1 (compile-time)
        const int dx = s - 3 * qy - 1;
        int rowbase = qy * 2376 + (m_base + dx + 1) * 36 + lanepart;
        unsigned aaddr0 = sbase + (unsigned)rowbase * 4;
        unsigned aaddr1 = aaddr0 + 16 * 36 * 4;
        const uint2* bs = bwarp + s * 2048;

#pragma unroll
        for (int kf = 0; kf < 4; ++kf) {
            uint2 bb0 = bs[(kf << 9)];
            uint2 bb1 = bs[(kf << 9) + 32];
            uint2 bb2 = bs[(kf << 9) + 64];
            uint2 bb3 = bs[(kf << 9) + 96];
            unsigned a0[4], a1[4];
            ldm_x4(a0, aaddr0 + (unsigned)(kf * 32));
            ldm_x4(a1, aaddr1 + (unsigned)(kf * 32));
            MMA_F16(acc[0][0], a0, bb0.x, bb0.y);
            MMA_F16(acc[1][0], a1, bb0.x, bb0.y);
            MMA_F16(acc[0][1], a0, bb1.x, bb1.y);
            MMA_F16(acc[1][1], a1, bb1.x, bb1.y);
            MMA_F16(acc[0][2], a0, bb2.x, bb2.y);
            MMA_F16(acc[1][2], a1, bb2.x, bb2.y);
            MMA_F16(acc[0][3], a0, bb3.x, bb3.y);
            MMA_F16(acc[1][3], a1, bb3.x, bb3.y);
        }
    }

    // ---- epilogue (no smem, no barriers: thread owns i,f,g,o) ------------
    if (MODE == 0) {
        // gates -> gout gate-minor [pix][f][4], + bias
        float bi[2][4];
#pragma unroll
        for (int j = 0; j < 2; ++j)
#pragma unroll
            for (int k = 0; k < 4; ++k)
                bi[j][k] = xg_or_bias[k * 64 + fglob + j];
#pragma unroll
        for (int mi = 0; mi < 2; ++mi)
#pragma unroll
            for (int rh = 0; rh < 2; ++rh) {
                int pix = y0 * 64 + m_base + mi * 16 + rh * 8 + g;
                float* ob = gout + ((size_t)img * NPIX + pix) * 256 + (size_t)fglob * 4;
                int cb = rh * 2;
#pragma unroll
                for (int j = 0; j < 2; ++j) {
                    float4 v = make_float4(acc[mi][0][cb + j] + bi[j][0],
                                           acc[mi][1][cb + j] + bi[j][1],
                                           acc[mi][2][cb + j] + bi[j][2],
                                           acc[mi][3][cb + j] + bi[j][3]);
                    *(float4*)(ob + j * 4) = v;
                }
            }
    } else {
#pragma unroll
        for (int mi = 0; mi < 2; ++mi)
#pragma unroll
            for (int rh = 0; rh < 2; ++rh) {
                int pix = y0 * 64 + m_base + mi * 16 + rh * 8 + g;
                const float4* xq = (const float4*)(xg_or_bias +
                    ((size_t)(img * 10 + tstep) * NPIX + pix) * 256 + (size_t)fglob * 4);
                float4 q0 = xq[0], q1 = xq[1];          // (i,f,g,o) for ch, ch+1
                size_t hoff = ((size_t)img * NPIX + pix) * 64 + fglob;
                float2 co = *(const float2*)(cbuf + hoff);
                int cb = rh * 2;
                float cn0 = hsig(acc[mi][1][cb] + q0.y) * co.x
                          + hsig(acc[mi][0][cb] + q0.x) * tanhf(acc[mi][2][cb] + q0.z);
                float cn1 = hsig(acc[mi][1][cb + 1] + q1.y) * co.y
                          + hsig(acc[mi][0][cb + 1] + q1.x) * tanhf(acc[mi][2][cb + 1] + q1.z);
                float hn0 = hsig(acc[mi][3][cb] + q0.w) * tanhf(cn0);
                float hn1 = hsig(acc[mi][3][cb + 1] + q1.w) * tanhf(cn1);
                __half2 hh = __floats2half2_rn(hn0, hn1);
                if (finalout) {                      // t=9: write fp32 h,c to d_out
                    *(float2*)(finalout + hoff)       = make_float2(hn0, hn1);
                    *(float2*)(finalout + SEG + hoff) = make_float2(cn0, cn1);
                } else {
                    *(float2*)(cbuf + hoff) = make_float2(cn0, cn1);
                    *(__half2*)(hout + hoff) = hh;
                }
                if (outseq)
                    *(__half2*)(outseq + ((size_t)(img * 10 + tstep) * NPIX + pix) * 64
                                + fglob) = hh;
            }
    }
}

// ---------------------------------------------------------------------------
extern "C" void kernel_launch(void* const* d_in, const int* in_sizes, int n_in,
                              void* d_out, int out_size) {
    const float* x   = (const float*)d_in[0];
    const float* Wx0 = (const float*)d_in[1];
    const float* Wh0 = (const float*)d_in[2];
    const float* b0  = (const float*)d_in[3];
    const float* Wx1 = (const float*)d_in[4];
    const float* Wh1 = (const float*)d_in[5];
    const float* b1  = (const float*)d_in[6];
    float* out = (float*)d_out;

    float *xg0, *xg1, *cb;
    __half *out0, *hbase;
    uint2* wt;
    cudaGetSymbolAddress((void**)&xg0,   g_xg0);
    cudaGetSymbolAddress((void**)&xg1,   g_xg1);
    cudaGetSymbolAddress((void**)&out0,  g_out0H);
    cudaGetSymbolAddress((void**)&hbase, g_hH);
    cudaGetSymbolAddress((void**)&cb,    g_c);
    cudaGetSymbolAddress((void**)&wt,    g_wtH);
    __half* hb[2] = { hbase, hbase + SEG };

    cudaFuncSetAttribute(mm_conv<1>, cudaFuncAttributeMaxDynamicSharedMemorySize, SMEM_BYTES);
    cudaFuncSetAttribute(mm_conv<0>, cudaFuncAttributeMaxDynamicSharedMemorySize, SMEM_BYTES);

    // fp16 fragment-order gate-interleaved weights: [0]=Wh0, [1]=Wx1, [2]=Wh1
    prep_w<<<432, 256>>>(Wh0, Wx1, Wh1);

    // Layer-0 input conv (exact fp32, gate-minor xg)
    conv_l0<<<dim3(16, 80), 256>>>(x, Wx0, b0, xg0);

    // Layer 0: t=0 exact init, t=1..8 steps, t=9 step writes d_out layer 0
    lstm_init<<<2048, 256>>>(xg0, cb, hb[1], out0);
    for (int t = 1; t < 9; ++t)
        mm_conv<1><<<dim3(128, 8), 256, SMEM_BYTES>>>(
            hb[t & 1], wt, xg0, nullptr, cb, hb[(t + 1) & 1], out0, nullptr, t);
    mm_conv<1><<<dim3(128, 8), 256, SMEM_BYTES>>>(
        hb[1], wt, xg0, nullptr, cb, nullptr, out0, out, 9);

    // Layer-1 batched input conv over 80 images (produces gate-minor xg1)
    mm_conv<0><<<dim3(128, 80), 256, SMEM_BYTES>>>(
        out0, wt + 36864, b1, xg1, nullptr, nullptr, nullptr, nullptr, 0);

    // Layer 1: t=0 exact init, t=1..8 steps, t=9 step writes d_out layer 1
    lstm_init<<<2048, 256>>>(xg1, cb, hb[1], nullptr);
    for (int t = 1; t < 9; ++t)
        mm_conv<1><<<dim3(128, 8), 256, SMEM_BYTES>>>(
            hb[t & 1], wt + 2 * 36864, xg1, nullptr, cb, hb[(t + 1) & 1], nullptr,
            nullptr, t);
    mm_conv<1><<<dim3(128, 8), 256, SMEM_BYTES>>>(
        hb[1], wt + 2 * 36864, xg1, nullptr, cb, nullptr, nullptr, out + 2 * SEG, 9);

    (void)in_sizes; (void)n_in; (void)out_size;
}